// round 4
// baseline (speedup 1.0000x reference)
#include <cuda_runtime.h>
#include <math.h>

// ---------------- scratch (device globals, no allocation) ----------------
__device__ float g_assign[8 * 64 * 1600];          // [b][k][n]
__device__ float g_vpart[25 * 8 * 32768];          // [ntile][b][d*64+k] vlad partials
__device__ float g_vlad[8 * 32768];                // [b][d][k] summed + PRE-SCALED desc
__device__ float g_wpart[2 * 8 * 4096];            // [ksplit][b][out] whiten partials

#define EPSN 1e-12f

// packed fp32x2 FMA: acc = a*b + acc
__device__ __forceinline__ void ffma2(unsigned long long& acc,
                                      unsigned long long a,
                                      unsigned long long b) {
    asm("fma.rn.f32x2 %0, %1, %2, %0;" : "+l"(acc) : "l"(a), "l"(b));
}

// ---------------- scores GEMM + softmax over K ----------------
// grid (50, 8): n-tile of 32, batch. block 128 = 16 k-groups x 8 n-groups, 4x4 each.
__global__ __launch_bounds__(128) void k_scores(const float* __restrict__ x,
                                                const float* __restrict__ cw) {
    const int b = blockIdx.y;
    const int n0 = blockIdx.x * 32;

    __shared__ __align__(16) float cs[32][68];  // [dd][kk]
    __shared__ __align__(16) float fs[32][36];  // [dd][nn]
    __shared__ __align__(16) float sm[64][33];  // scores [k][n]
    __shared__ float inv_sum[32];

    const int tx = threadIdx.x & 7;    // n group (4 n each)
    const int ty = threadIdx.x >> 3;   // k group (4 k each)

    float acc[4][4];
#pragma unroll
    for (int i = 0; i < 4; i++)
#pragma unroll
        for (int j = 0; j < 4; j++) acc[i][j] = 0.0f;

    const float* xb = x + (size_t)b * 512 * 1600;

    for (int d0 = 0; d0 < 512; d0 += 32) {
        __syncthreads();
        for (int idx = threadIdx.x; idx < 2048; idx += 128) {
            int k = idx >> 5, dd = idx & 31;
            cs[dd][k] = cw[k * 512 + d0 + dd];
        }
        for (int idx = threadIdx.x; idx < 1024; idx += 128) {
            int dd = idx >> 5, nn = idx & 31;
            fs[dd][nn] = xb[(size_t)(d0 + dd) * 1600 + n0 + nn];
        }
        __syncthreads();
#pragma unroll 8
        for (int dd = 0; dd < 32; dd++) {
            float4 a = *(const float4*)&cs[dd][ty * 4];
            float4 f = *(const float4*)&fs[dd][tx * 4];
            acc[0][0] += a.x * f.x; acc[0][1] += a.x * f.y; acc[0][2] += a.x * f.z; acc[0][3] += a.x * f.w;
            acc[1][0] += a.y * f.x; acc[1][1] += a.y * f.y; acc[1][2] += a.y * f.z; acc[1][3] += a.y * f.w;
            acc[2][0] += a.z * f.x; acc[2][1] += a.z * f.y; acc[2][2] += a.z * f.z; acc[2][3] += a.z * f.w;
            acc[3][0] += a.w * f.x; acc[3][1] += a.w * f.y; acc[3][2] += a.w * f.z; acc[3][3] += a.w * f.w;
        }
    }
    __syncthreads();
#pragma unroll
    for (int i = 0; i < 4; i++)
#pragma unroll
        for (int j = 0; j < 4; j++) sm[ty * 4 + i][tx * 4 + j] = acc[i][j];
    __syncthreads();

    // softmax over k, one thread per n column (warp 0)
    if (threadIdx.x < 32) {
        const int n = threadIdx.x;
        float mx = -1e30f;
#pragma unroll 8
        for (int k = 0; k < 64; k++) mx = fmaxf(mx, sm[k][n]);
        float s = 0.0f;
#pragma unroll 8
        for (int k = 0; k < 64; k++) {
            float e = __expf(sm[k][n] - mx);
            sm[k][n] = e;
            s += e;
        }
        inv_sum[n] = 1.0f / s;
    }
    __syncthreads();

    float* ab = g_assign + (size_t)b * 64 * 1600 + n0;
    for (int idx = threadIdx.x; idx < 2048; idx += 128) {
        int k = idx >> 5, nn = idx & 31;
        ab[(size_t)k * 1600 + nn] = sm[k][nn] * inv_sum[nn];
    }
}

// ---------------- VLAD GEMM (one 64-n chunk per CTA) + centers term ----------------
// grid (25, 8, 8): n-tile (64), d-tile (64), batch. block 256 = 16x16, 4x4 each.
__global__ __launch_bounds__(256) void k_vlad(const float* __restrict__ x,
                                              const float* __restrict__ centers) {
    const int b = blockIdx.z;
    const int d0 = blockIdx.y * 64;
    const int nb = blockIdx.x * 64;

    __shared__ __align__(16) float fs[64][68];   // [nn][dd]
    __shared__ __align__(16) float as_[64][68];  // [nn][kk]
    __shared__ float asum_s[64];

    const int tx = threadIdx.x & 15;  // k group
    const int ty = threadIdx.x >> 4;  // d group

    float acc[4][4];
#pragma unroll
    for (int i = 0; i < 4; i++)
#pragma unroll
        for (int j = 0; j < 4; j++) acc[i][j] = 0.0f;

    const float* xb = x + (size_t)b * 512 * 1600;
    const float* ab = g_assign + (size_t)b * 64 * 1600;

    for (int idx = threadIdx.x; idx < 4096; idx += 256) {
        int dd = idx >> 6, nn = idx & 63;
        fs[nn][dd] = xb[(size_t)(d0 + dd) * 1600 + nb + nn];
    }
    for (int idx = threadIdx.x; idx < 4096; idx += 256) {
        int kk = idx >> 6, nn = idx & 63;
        as_[nn][kk] = ab[(size_t)kk * 1600 + nb + nn];
    }
    __syncthreads();

#pragma unroll 8
    for (int nn = 0; nn < 64; nn++) {
        float4 f = *(const float4*)&fs[nn][ty * 4];
        float4 a = *(const float4*)&as_[nn][tx * 4];
        acc[0][0] += f.x * a.x; acc[0][1] += f.x * a.y; acc[0][2] += f.x * a.z; acc[0][3] += f.x * a.w;
        acc[1][0] += f.y * a.x; acc[1][1] += f.y * a.y; acc[1][2] += f.y * a.z; acc[1][3] += f.y * a.w;
        acc[2][0] += f.z * a.x; acc[2][1] += f.z * a.y; acc[2][2] += f.z * a.z; acc[2][3] += f.z * a.w;
        acc[3][0] += f.w * a.x; acc[3][1] += f.w * a.y; acc[3][2] += f.w * a.z; acc[3][3] += f.w * a.w;
    }

    if (threadIdx.x < 64) {
        float s = 0.0f;
#pragma unroll 8
        for (int nn = 0; nn < 64; nn++) s += as_[nn][threadIdx.x];
        asum_s[threadIdx.x] = s;
    }
    __syncthreads();

    float* vb = g_vpart + ((size_t)blockIdx.x * 8 + b) * 32768;
#pragma unroll
    for (int i = 0; i < 4; i++) {
        const int d = d0 + ty * 4 + i;
#pragma unroll
        for (int j = 0; j < 4; j++) {
            const int k = tx * 4 + j;
            vb[d * 64 + k] = acc[i][j] - asum_s[k] * centers[d * 64 + k];
        }
    }
}

// ---------------- sum 25 partials + intra-norm + global norm + PRE-SCALE ----------------
// grid 8 (batch), block 512 = 64 k x 8 dy
__global__ __launch_bounds__(512) void k_norm() {
    const int b = blockIdx.x;
    const int kx = threadIdx.x & 63;
    const int dy = threadIdx.x >> 6;
    float* vb = g_vlad + (size_t)b * 32768;

    float ss = 0.0f;
    for (int d = dy; d < 512; d += 8) {
        const int i = d * 64 + kx;
        float v = 0.0f;
#pragma unroll
        for (int s = 0; s < 25; s++) v += g_vpart[((size_t)s * 8 + b) * 32768 + i];
        vb[i] = v;
        ss += v * v;
    }

    __shared__ float red[8][64];
    __shared__ float cs_s[64];
    __shared__ float contrib[64];
    __shared__ float ginv;
    red[dy][kx] = ss;
    __syncthreads();
    if (dy == 0) {
        float t = 0.0f;
#pragma unroll
        for (int r = 0; r < 8; r++) t += red[r][kx];
        float inv = 1.0f / fmaxf(sqrtf(t), EPSN);
        cs_s[kx] = inv;
        contrib[kx] = t * inv * inv;
    }
    __syncthreads();
    if (threadIdx.x == 0) {
        float g = 0.0f;
#pragma unroll
        for (int k = 0; k < 64; k++) g += contrib[k];
        ginv = 1.0f / fmaxf(sqrtf(g), EPSN);
    }
    __syncthreads();

    const float sc = cs_s[kx] * ginv;
    for (int d = dy; d < 512; d += 8) vb[d * 64 + kx] *= sc;
}

// ---------------- whitening GEMM: K-split x2, 16 rows/CTA ----------------
// grid 512 = 256 row-tiles x 2 K-halves. block 256 (8 warps x 2 rows each).
__global__ __launch_bounds__(256) void k_whiten(const float* __restrict__ W) {
    __shared__ __align__(16) float dsc[8][1024];  // b-major desc tile (pre-scaled)

    const int rowtile = blockIdx.x >> 1;
    const int ks = blockIdx.x & 1;
    const int o0 = rowtile * 16;
    const int jbase = ks * 16384;

    const int lane = threadIdx.x & 31;
    const int warp = threadIdx.x >> 5;
    const int row0 = o0 + warp * 2;

    unsigned long long acc2[2][8];
#pragma unroll
    for (int r = 0; r < 2; r++)
#pragma unroll
        for (int bb = 0; bb < 8; bb++) acc2[r][bb] = 0ULL;

    const float4* __restrict__ vlad4 = (const float4*)g_vlad;

    for (int jt = jbase; jt < jbase + 16384; jt += 1024) {
        __syncthreads();
        for (int idx = threadIdx.x; idx < 2048; idx += 256) {
            int bb = idx >> 8;
            int q = idx & 255;
            *(float4*)&dsc[bb][q << 2] = vlad4[bb * 8192 + (jt >> 2) + q];
        }
        __syncthreads();

        const float* Wp = W + (size_t)row0 * 32768 + jt;
        ulonglong2 wbuf[2][2];
#pragma unroll
        for (int r = 0; r < 2; r++)
            wbuf[0][r] = *(const ulonglong2*)(Wp + (size_t)r * 32768 + lane * 4);

#pragma unroll
        for (int s = 0; s < 8; s++) {
            const int cur = s & 1;
            if (s < 7) {
                const int jn = (s + 1) * 128 + lane * 4;
#pragma unroll
                for (int r = 0; r < 2; r++)
                    wbuf[cur ^ 1][r] = *(const ulonglong2*)(Wp + (size_t)r * 32768 + jn);
            }
            const int jj = s * 128 + lane * 4;
#pragma unroll
            for (int bb = 0; bb < 8; bb++) {
                ulonglong2 d = *(const ulonglong2*)&dsc[bb][jj];
#pragma unroll
                for (int r = 0; r < 2; r++) {
                    ffma2(acc2[r][bb], wbuf[cur][r].x, d.x);
                    ffma2(acc2[r][bb], wbuf[cur][r].y, d.y);
                }
            }
        }
    }

    // collapse packed halves + butterfly reduce; lanes 0..15 write (2 rows x 8 b)
    float accf[2][8];
#pragma unroll
    for (int r = 0; r < 2; r++)
#pragma unroll
        for (int bb = 0; bb < 8; bb++) {
            float2 f = *reinterpret_cast<float2*>(&acc2[r][bb]);
            float v = f.x + f.y;
#pragma unroll
            for (int off = 16; off; off >>= 1)
                v += __shfl_xor_sync(0xffffffffu, v, off);
            accf[r][bb] = v;
        }

    if (lane < 16) {
        const int r = lane >> 3;
        const int bsel = lane & 7;
        float res = 0.0f;
#pragma unroll
        for (int rr = 0; rr < 2; rr++)
#pragma unroll
            for (int bb = 0; bb < 8; bb++)
                if (rr == r && bb == bsel) res = accf[rr][bb];
        g_wpart[((size_t)ks * 8 + bsel) * 4096 + row0 + r] = res;
    }
}

// ---------------- combine K-halves + bias + final per-row L2 norm ----------------
__global__ __launch_bounds__(256) void k_final(const float* __restrict__ bias,
                                               float* __restrict__ out) {
    const int b = blockIdx.x;
    float v[16];
    float ss = 0.0f;
#pragma unroll
    for (int t = 0; t < 16; t++) {
        const int o = threadIdx.x + t * 256;
        float val = g_wpart[(size_t)b * 4096 + o] +
                    g_wpart[(size_t)(8 + b) * 4096 + o] + bias[o];
        v[t] = val;
        ss += val * val;
    }
#pragma unroll
    for (int off = 16; off; off >>= 1) ss += __shfl_xor_sync(0xffffffffu, ss, off);
    __shared__ float r[8];
    __shared__ float sc;
    const int lane = threadIdx.x & 31, warp = threadIdx.x >> 5;
    if (lane == 0) r[warp] = ss;
    __syncthreads();
    if (threadIdx.x == 0) {
        float t = 0.0f;
#pragma unroll
        for (int i = 0; i < 8; i++) t += r[i];
        sc = 1.0f / fmaxf(sqrtf(t), EPSN);
    }
    __syncthreads();
    float* ob = out + (size_t)b * 4096;
#pragma unroll
    for (int t = 0; t < 16; t++) ob[threadIdx.x + t * 256] = v[t] * sc;
}

// ---------------- launch ----------------
extern "C" void kernel_launch(void* const* d_in, const int* in_sizes, int n_in,
                              void* d_out, int out_size) {
    const float* x        = (const float*)d_in[0];
    const float* conv_w   = (const float*)d_in[1];
    const float* centers  = (const float*)d_in[2];
    const float* whiten_w = (const float*)d_in[3];
    const float* whiten_b = (const float*)d_in[4];
    float* out = (float*)d_out;

    k_scores<<<dim3(50, 8), 128>>>(x, conv_w);
    k_vlad<<<dim3(25, 8, 8), 256>>>(x, centers);
    k_norm<<<8, 512>>>();
    k_whiten<<<512, 256>>>(whiten_w);
    k_final<<<8, 256>>>(whiten_b, out);
}

// round 5
// speedup vs baseline: 1.5430x; 1.5430x over previous
#include <cuda_runtime.h>
#include <math.h>
#include <stdint.h>

// ---------------- scratch (device globals, no allocation) ----------------
__device__ float g_assign[8 * 64 * 1600];   // [b][k][n]
__device__ float g_vpart[5 * 8 * 32768];    // [nsplit][b][d*64+k] vlad partials
__device__ float g_vlad[8 * 32768];         // [b][d][k] summed + PRE-SCALED desc
__device__ float g_wpart[2 * 8 * 4096];     // [ksplit][b][out] whiten partials

#define EPSN 1e-12f

// packed fp32x2 FMA: acc = a*b + acc
__device__ __forceinline__ void ffma2(unsigned long long& acc,
                                      unsigned long long a,
                                      unsigned long long b) {
    asm("fma.rn.f32x2 %0, %1, %2, %0;" : "+l"(acc) : "l"(a), "l"(b));
}
// broadcast one float into a packed pair (ALU pipe, overlaps FMA)
__device__ __forceinline__ unsigned long long pack2(float v) {
    unsigned long long r;
    asm("mov.b64 %0, {%1, %1};" : "=l"(r) : "f"(v));
    return r;
}
__device__ __forceinline__ float2 unpack2(unsigned long long v) {
    float2 f;
    asm("mov.b64 {%0, %1}, %2;" : "=f"(f.x), "=f"(f.y) : "l"(v));
    return f;
}
// 16B async copy gmem -> smem (bypasses L1, lands in smem)
__device__ __forceinline__ void cpa16(uint32_t s, const void* g) {
    asm volatile("cp.async.cg.shared.global [%0], [%1], 16;" :: "r"(s), "l"(g));
}
__device__ __forceinline__ void cpa_commit() {
    asm volatile("cp.async.commit_group;");
}

// ---------------- scores GEMM + softmax over K ----------------
// grid (25, 8): n-tile of 64, batch. block 256 = 16x16, 4k x 4n per thread.
__global__ __launch_bounds__(256) void k_scores(const float* __restrict__ x,
                                                const float* __restrict__ cw) {
    const int b = blockIdx.y;
    const int n0 = blockIdx.x * 64;

    __shared__ __align__(16) float cs[32][68];  // [dd][kk]
    __shared__ __align__(16) float fs[32][68];  // [dd][nn]
    __shared__ __align__(16) float sm[64][65];  // scores [k][n]
    __shared__ float inv_sum[64];

    const int tx = threadIdx.x & 15;   // n group
    const int ty = threadIdx.x >> 4;   // k group

    unsigned long long acc2[4][2];     // [k][npair]
#pragma unroll
    for (int i = 0; i < 4; i++) { acc2[i][0] = 0ULL; acc2[i][1] = 0ULL; }

    const float* xb = x + (size_t)b * 512 * 1600;

    for (int d0 = 0; d0 < 512; d0 += 32) {
        __syncthreads();
        for (int idx = threadIdx.x; idx < 2048; idx += 256) {
            int k = idx >> 5, dd = idx & 31;
            cs[dd][k] = cw[k * 512 + d0 + dd];
        }
        for (int idx = threadIdx.x; idx < 2048; idx += 256) {
            int dd = idx >> 6, nn = idx & 63;
            fs[dd][nn] = xb[(size_t)(d0 + dd) * 1600 + n0 + nn];
        }
        __syncthreads();
#pragma unroll 8
        for (int dd = 0; dd < 32; dd++) {
            float4 a = *(const float4*)&cs[dd][ty * 4];
            ulonglong2 f2 = *(const ulonglong2*)&fs[dd][tx * 4];
            unsigned long long a0 = pack2(a.x), a1 = pack2(a.y),
                               a2 = pack2(a.z), a3 = pack2(a.w);
            ffma2(acc2[0][0], a0, f2.x); ffma2(acc2[0][1], a0, f2.y);
            ffma2(acc2[1][0], a1, f2.x); ffma2(acc2[1][1], a1, f2.y);
            ffma2(acc2[2][0], a2, f2.x); ffma2(acc2[2][1], a2, f2.y);
            ffma2(acc2[3][0], a3, f2.x); ffma2(acc2[3][1], a3, f2.y);
        }
    }
    __syncthreads();
#pragma unroll
    for (int i = 0; i < 4; i++)
#pragma unroll
        for (int p = 0; p < 2; p++) {
            float2 u = unpack2(acc2[i][p]);
            sm[ty * 4 + i][tx * 4 + 2 * p]     = u.x;
            sm[ty * 4 + i][tx * 4 + 2 * p + 1] = u.y;
        }
    __syncthreads();

    if (threadIdx.x < 64) {
        const int n = threadIdx.x;
        float mx = -1e30f;
#pragma unroll 8
        for (int k = 0; k < 64; k++) mx = fmaxf(mx, sm[k][n]);
        float s = 0.0f;
#pragma unroll 8
        for (int k = 0; k < 64; k++) {
            float e = __expf(sm[k][n] - mx);
            sm[k][n] = e;
            s += e;
        }
        inv_sum[n] = 1.0f / s;
    }
    __syncthreads();

    float* ab = g_assign + (size_t)b * 64 * 1600 + n0;
    for (int idx = threadIdx.x; idx < 4096; idx += 256) {
        int k = idx >> 6, nn = idx & 63;
        ab[(size_t)k * 1600 + nn] = sm[k][nn] * inv_sum[nn];
    }
}

// ---------------- VLAD GEMM (partial over n-split) + centers term ----------------
// grid (5, 8, 8): n-split (320 n each), d-tile (64), batch. block 256 = 16x16.
__global__ __launch_bounds__(256) void k_vlad(const float* __restrict__ x,
                                              const float* __restrict__ centers) {
    const int b = blockIdx.z;
    const int d0 = blockIdx.y * 64;
    const int n0 = blockIdx.x * 320;

    __shared__ __align__(16) float fs[64][68];   // [nn][dd]
    __shared__ __align__(16) float as_[64][68];  // [nn][kk]
    __shared__ float asum_s[64];

    const int tx = threadIdx.x & 15;  // k group
    const int ty = threadIdx.x >> 4;  // d group

    unsigned long long acc2[4][2];    // [d][kpair]
#pragma unroll
    for (int i = 0; i < 4; i++) { acc2[i][0] = 0ULL; acc2[i][1] = 0ULL; }
    float asum_acc = 0.0f;

    const float* xb = x + (size_t)b * 512 * 1600;
    const float* ab = g_assign + (size_t)b * 64 * 1600;

    for (int c = 0; c < 5; c++) {
        const int nb = n0 + c * 64;
        __syncthreads();
        for (int idx = threadIdx.x; idx < 4096; idx += 256) {
            int dd = idx >> 6, nn = idx & 63;
            fs[nn][dd] = xb[(size_t)(d0 + dd) * 1600 + nb + nn];
        }
        for (int idx = threadIdx.x; idx < 4096; idx += 256) {
            int kk = idx >> 6, nn = idx & 63;
            as_[nn][kk] = ab[(size_t)kk * 1600 + nb + nn];
        }
        __syncthreads();
#pragma unroll 8
        for (int nn = 0; nn < 64; nn++) {
            float4 f = *(const float4*)&fs[nn][ty * 4];
            ulonglong2 a2 = *(const ulonglong2*)&as_[nn][tx * 4];
            unsigned long long f0 = pack2(f.x), f1 = pack2(f.y),
                               f2p = pack2(f.z), f3 = pack2(f.w);
            ffma2(acc2[0][0], f0, a2.x);  ffma2(acc2[0][1], f0, a2.y);
            ffma2(acc2[1][0], f1, a2.x);  ffma2(acc2[1][1], f1, a2.y);
            ffma2(acc2[2][0], f2p, a2.x); ffma2(acc2[2][1], f2p, a2.y);
            ffma2(acc2[3][0], f3, a2.x);  ffma2(acc2[3][1], f3, a2.y);
        }
        if (threadIdx.x < 64) {
#pragma unroll 8
            for (int nn = 0; nn < 64; nn++) asum_acc += as_[nn][threadIdx.x];
        }
    }
    if (threadIdx.x < 64) asum_s[threadIdx.x] = asum_acc;
    __syncthreads();

    float* vb = g_vpart + ((size_t)blockIdx.x * 8 + b) * 32768;
#pragma unroll
    for (int i = 0; i < 4; i++) {
        const int d = d0 + ty * 4 + i;
#pragma unroll
        for (int p = 0; p < 2; p++) {
            float2 u = unpack2(acc2[i][p]);
            const int k = tx * 4 + 2 * p;
            vb[d * 64 + k]     = u.x - asum_s[k] * centers[d * 64 + k];
            vb[d * 64 + k + 1] = u.y - asum_s[k + 1] * centers[d * 64 + k + 1];
        }
    }
}

// ---------------- sum partials + intra-norm + global norm + PRE-SCALE ----------------
// grid 8 (batch), block 512 = 64 k x 8 dy
__global__ __launch_bounds__(512) void k_norm() {
    const int b = blockIdx.x;
    const int kx = threadIdx.x & 63;
    const int dy = threadIdx.x >> 6;
    float* vb = g_vlad + (size_t)b * 32768;

    float ss = 0.0f;
    for (int d = dy; d < 512; d += 8) {
        const int i = d * 64 + kx;
        float v = 0.0f;
#pragma unroll
        for (int s = 0; s < 5; s++) v += g_vpart[((size_t)s * 8 + b) * 32768 + i];
        vb[i] = v;
        ss += v * v;
    }

    __shared__ float red[8][64];
    __shared__ float cs_s[64];
    __shared__ float contrib[64];
    __shared__ float ginv;
    red[dy][kx] = ss;
    __syncthreads();
    if (dy == 0) {
        float t = 0.0f;
#pragma unroll
        for (int r = 0; r < 8; r++) t += red[r][kx];
        float inv = 1.0f / fmaxf(sqrtf(t), EPSN);
        cs_s[kx] = inv;
        contrib[kx] = t * inv * inv;
    }
    __syncthreads();
    if (threadIdx.x == 0) {
        float g = 0.0f;
#pragma unroll
        for (int k = 0; k < 64; k++) g += contrib[k];
        ginv = 1.0f / fmaxf(sqrtf(g), EPSN);
    }
    __syncthreads();

    const float sc = cs_s[kx] * ginv;
    for (int d = dy; d < 512; d += 8) vb[d * 64 + kx] *= sc;
}

// ---------------- whitening GEMM: cp.async double-buffered pipeline ----------------
// grid 256 = 128 rowtiles(32 rows) x 2 K-halves. block 256 (8 warps x 4 rows).
// Tiles of 128 cols: Wbuf[2][32][128] + Dbuf[2][8][128] = 40KB static smem.
__global__ __launch_bounds__(256, 2) void k_whiten(const float* __restrict__ W) {
    __shared__ __align__(16) float Wsm[2][32][128];
    __shared__ __align__(16) float Dsm[2][8][128];

    const int rowtile = blockIdx.x >> 1;
    const int ks = blockIdx.x & 1;
    const int o0 = rowtile * 32;
    const int jbase = ks * 16384;

    const int tid = threadIdx.x;
    const int lane = tid & 31;
    const int warp = tid >> 5;
    const int r0 = warp * 4;
    const int c = lane * 4;

    unsigned long long acc2[4][8];
#pragma unroll
    for (int r = 0; r < 4; r++)
#pragma unroll
        for (int bb = 0; bb < 8; bb++) acc2[r][bb] = 0ULL;

    // staging indices (fixed per thread)
    const int wr  = tid >> 5;          // rows 0..7 handled 4x (idx stride 256)
    const int wc4 = tid & 31;          // float4 col 0..31

    uint32_t sW[2], sD[2];
    sW[0] = (uint32_t)__cvta_generic_to_shared(&Wsm[0][0][0]);
    sW[1] = (uint32_t)__cvta_generic_to_shared(&Wsm[1][0][0]);
    sD[0] = (uint32_t)__cvta_generic_to_shared(&Dsm[0][0][0]);
    sD[1] = (uint32_t)__cvta_generic_to_shared(&Dsm[1][0][0]);

    const float* Wbase = W + (size_t)o0 * 32768 + jbase;
    const float* Dbase = g_vlad + jbase;

    // stage tile t into buffer buf
    auto stage = [&](int t, int buf) {
        const int jc = t * 128 + wc4 * 4;
#pragma unroll
        for (int i = 0; i < 4; i++) {
            const int r = wr + i * 8;
            cpa16(sW[buf] + (uint32_t)(r * 128 + wc4 * 4) * 4,
                  Wbase + (size_t)r * 32768 + jc);
        }
        const int bb = tid >> 5;  // 8 warps -> 8 batches
        cpa16(sD[buf] + (uint32_t)(bb * 128 + wc4 * 4) * 4,
              Dbase + (size_t)bb * 32768 + jc);
        cpa_commit();
    };

    stage(0, 0);

    for (int t = 0; t < 128; t++) {
        const int buf = t & 1;
        if (t < 127) {
            stage(t + 1, buf ^ 1);
            asm volatile("cp.async.wait_group 1;");
        } else {
            asm volatile("cp.async.wait_group 0;");
        }
        __syncthreads();

        ulonglong2 w2[4];
#pragma unroll
        for (int r = 0; r < 4; r++)
            w2[r] = *(const ulonglong2*)&Wsm[buf][r0 + r][c];
#pragma unroll
        for (int bb = 0; bb < 8; bb++) {
            ulonglong2 d2 = *(const ulonglong2*)&Dsm[buf][bb][c];
#pragma unroll
            for (int r = 0; r < 4; r++) {
                ffma2(acc2[r][bb], w2[r].x, d2.x);
                ffma2(acc2[r][bb], w2[r].y, d2.y);
            }
        }
        __syncthreads();
    }

    // collapse packed halves + butterfly reduce; lanes 0..31 = 4 rows x 8 b
    float accf[4][8];
#pragma unroll
    for (int r = 0; r < 4; r++)
#pragma unroll
        for (int bb = 0; bb < 8; bb++) {
            float2 f = unpack2(acc2[r][bb]);
            float v = f.x + f.y;
#pragma unroll
            for (int off = 16; off; off >>= 1)
                v += __shfl_xor_sync(0xffffffffu, v, off);
            accf[r][bb] = v;
        }

    const int rr = lane >> 3;
    const int bsel = lane & 7;
    float res = 0.0f;
#pragma unroll
    for (int r = 0; r < 4; r++)
#pragma unroll
        for (int bb = 0; bb < 8; bb++)
            if (r == rr && bb == bsel) res = accf[r][bb];

    g_wpart[((size_t)ks * 8 + bsel) * 4096 + o0 + r0 + rr] = res;
}

// ---------------- combine K-halves + bias + final per-row L2 norm ----------------
__global__ __launch_bounds__(256) void k_final(const float* __restrict__ bias,
                                               float* __restrict__ out) {
    const int b = blockIdx.x;
    float v[16];
    float ss = 0.0f;
#pragma unroll
    for (int t = 0; t < 16; t++) {
        const int o = threadIdx.x + t * 256;
        float val = g_wpart[(size_t)b * 4096 + o] +
                    g_wpart[(size_t)(8 + b) * 4096 + o] + bias[o];
        v[t] = val;
        ss += val * val;
    }
#pragma unroll
    for (int off = 16; off; off >>= 1) ss += __shfl_xor_sync(0xffffffffu, ss, off);
    __shared__ float r[8];
    __shared__ float sc;
    const int lane = threadIdx.x & 31, warp = threadIdx.x >> 5;
    if (lane == 0) r[warp] = ss;
    __syncthreads();
    if (threadIdx.x == 0) {
        float t = 0.0f;
#pragma unroll
        for (int i = 0; i < 8; i++) t += r[i];
        sc = 1.0f / fmaxf(sqrtf(t), EPSN);
    }
    __syncthreads();
    float* ob = out + (size_t)b * 4096;
#pragma unroll
    for (int t = 0; t < 16; t++) ob[threadIdx.x + t * 256] = v[t] * sc;
}

// ---------------- launch ----------------
extern "C" void kernel_launch(void* const* d_in, const int* in_sizes, int n_in,
                              void* d_out, int out_size) {
    const float* x        = (const float*)d_in[0];
    const float* conv_w   = (const float*)d_in[1];
    const float* centers  = (const float*)d_in[2];
    const float* whiten_w = (const float*)d_in[3];
    const float* whiten_b = (const float*)d_in[4];
    float* out = (float*)d_out;

    k_scores<<<dim3(25, 8), 256>>>(x, conv_w);
    k_vlad<<<dim3(5, 8, 8), 256>>>(x, centers);
    k_norm<<<8, 512>>>();
    k_whiten<<<256, 256>>>(whiten_w);
    k_final<<<8, 256>>>(whiten_b, out);
}

// round 6
// speedup vs baseline: 1.7304x; 1.1214x over previous
#include <cuda_runtime.h>
#include <math.h>
#include <stdint.h>

// ---------------- scratch (device globals, no allocation) ----------------
__device__ float g_vlad[8 * 32768];     // [b][d*64+k]: raw gemm sums -> centered -> scaled
__device__ float g_asum[8 * 64];        // [b][k] total assign sums
__device__ float g_ksum[8 * 64];        // [b][k] sum of squares over d
__device__ float g_wpart[4 * 8 * 4096]; // [ksplit][b][out] whiten partials

#define EPSN 1e-12f
typedef unsigned long long ull;

__device__ __forceinline__ void ffma2(ull& acc, ull a, ull b) {
    asm("fma.rn.f32x2 %0, %1, %2, %0;" : "+l"(acc) : "l"(a), "l"(b));
}
__device__ __forceinline__ ull pack2(float v) {
    ull r; asm("mov.b64 %0, {%1, %1};" : "=l"(r) : "f"(v)); return r;
}
__device__ __forceinline__ float2 unpack2(ull v) {
    float2 f; asm("mov.b64 {%0, %1}, %2;" : "=f"(f.x), "=f"(f.y) : "l"(v)); return f;
}
__device__ __forceinline__ void cpa16(uint32_t s, const void* g) {
    asm volatile("cp.async.cg.shared.global [%0], [%1], 16;" :: "r"(s), "l"(g));
}
__device__ __forceinline__ void cpa_commit() { asm volatile("cp.async.commit_group;"); }

// ---------------- zero accumulators ----------------
__global__ void k_zero() {
    int i = blockIdx.x * 256 + threadIdx.x;
    if (i < 8 * 32768) g_vlad[i] = 0.0f;
    else if (i < 8 * 32768 + 512) g_asum[i - 8 * 32768] = 0.0f;
    else if (i < 8 * 32768 + 1024) g_ksum[i - 8 * 32768 - 512] = 0.0f;
}

// ---------------- fused scores + softmax + vlad-gemm ----------------
// grid (25, 8): n-tile of 64, batch. block 256 = 16x16. occ 2/SM -> single wave.
__global__ __launch_bounds__(256, 2) void k_fused(const float* __restrict__ x,
                                                  const float* __restrict__ cw) {
    const int b = blockIdx.y;
    const int n0 = blockIdx.x * 64;
    const int t = threadIdx.x;
    const int tx = t & 15;   // n-group (phase1) / k-group (phase2)
    const int ty = t >> 4;   // k-group (phase1) / d-group (phase2)

    // u1: xs(phase1) -> asT(phase2).  u2: cs(phase1) -> scores/assign -> xs(phase2)
    __shared__ __align__(16) float u1[64 * 68];
    __shared__ __align__(16) float u2[64 * 68];
    __shared__ float inv_sum[64];
#define XS(r, c_)  u1[(r) * 68 + (c_)]
#define CS(r, c_)  u2[(r) * 68 + (c_)]
#define SMM(r, c_) u2[(r) * 68 + (c_)]
#define AT(r, c_)  u1[(r) * 68 + (c_)]
#define XS2(r, c_) u2[(r) * 68 + (c_)]

    const float* xb = x + (size_t)b * 512 * 1600;

    // ---- phase 1: scores = cw @ x_tile ----
    ull acc[4][2];
#pragma unroll
    for (int i = 0; i < 4; i++) { acc[i][0] = 0ULL; acc[i][1] = 0ULL; }

    for (int d0 = 0; d0 < 512; d0 += 64) {
        __syncthreads();
        for (int idx = t; idx < 4096; idx += 256) {
            int k = idx >> 6, dd = idx & 63;
            CS(dd, k) = cw[k * 512 + d0 + dd];
        }
        for (int idx = t; idx < 4096; idx += 256) {
            int dd = idx >> 6, nn = idx & 63;
            XS(dd, nn) = xb[(size_t)(d0 + dd) * 1600 + n0 + nn];
        }
        __syncthreads();
#pragma unroll 8
        for (int dd = 0; dd < 64; dd++) {
            float4 a = *(const float4*)&CS(dd, ty * 4);
            ulonglong2 f2 = *(const ulonglong2*)&XS(dd, tx * 4);
            ull a0 = pack2(a.x), a1 = pack2(a.y), a2 = pack2(a.z), a3 = pack2(a.w);
            ffma2(acc[0][0], a0, f2.x); ffma2(acc[0][1], a0, f2.y);
            ffma2(acc[1][0], a1, f2.x); ffma2(acc[1][1], a1, f2.y);
            ffma2(acc[2][0], a2, f2.x); ffma2(acc[2][1], a2, f2.y);
            ffma2(acc[3][0], a3, f2.x); ffma2(acc[3][1], a3, f2.y);
        }
    }
    __syncthreads();
    // scores -> u2 (cs is dead)
#pragma unroll
    for (int i = 0; i < 4; i++)
#pragma unroll
        for (int p = 0; p < 2; p++) {
            float2 u = unpack2(acc[i][p]);
            SMM(ty * 4 + i, tx * 4 + 2 * p)     = u.x;
            SMM(ty * 4 + i, tx * 4 + 2 * p + 1) = u.y;
        }
    __syncthreads();

    // ---- softmax over k (column-wise), then normalize rows + asum ----
    if (t < 64) {
        const int n = t;
        float mx = -1e30f;
#pragma unroll 8
        for (int k = 0; k < 64; k++) mx = fmaxf(mx, SMM(k, n));
        float s = 0.0f;
#pragma unroll 8
        for (int k = 0; k < 64; k++) {
            float e = __expf(SMM(k, n) - mx);
            SMM(k, n) = e;
            s += e;
        }
        inv_sum[n] = 1.0f / s;
    }
    __syncthreads();
    if (t < 64) {
        const int k = t;
        float s = 0.0f;
#pragma unroll 8
        for (int nn = 0; nn < 64; nn++) {
            float a = SMM(k, nn) * inv_sum[nn];
            SMM(k, nn) = a;
            s += a;
        }
        atomicAdd(&g_asum[b * 64 + k], s);
    }
    __syncthreads();
    // transpose assign into u1 (xs is dead)
    for (int idx = t; idx < 4096; idx += 256) {
        int k = idx >> 6, nn = idx & 63;
        AT(nn, k) = SMM(k, nn);
    }

    // ---- phase 2: vlad partial = x_tile @ assign^T, RED into g_vlad ----
    float* vb = g_vlad + (size_t)b * 32768;
    for (int d0 = 0; d0 < 512; d0 += 64) {
        __syncthreads();   // protects AT build (first iter) and prior XS2 use
        for (int idx = t; idx < 4096; idx += 256) {
            int dd = idx >> 6, nn = idx & 63;
            XS2(dd, nn) = xb[(size_t)(d0 + dd) * 1600 + n0 + nn];
        }
        __syncthreads();

        ull acc2[4][2];
#pragma unroll
        for (int i = 0; i < 4; i++) { acc2[i][0] = 0ULL; acc2[i][1] = 0ULL; }
#pragma unroll 4
        for (int nn = 0; nn < 64; nn++) {
            ulonglong2 a2 = *(const ulonglong2*)&AT(nn, tx * 4);
            ull f0 = pack2(XS2(ty * 4 + 0, nn));
            ull f1 = pack2(XS2(ty * 4 + 1, nn));
            ull f2p = pack2(XS2(ty * 4 + 2, nn));
            ull f3 = pack2(XS2(ty * 4 + 3, nn));
            ffma2(acc2[0][0], f0, a2.x);  ffma2(acc2[0][1], f0, a2.y);
            ffma2(acc2[1][0], f1, a2.x);  ffma2(acc2[1][1], f1, a2.y);
            ffma2(acc2[2][0], f2p, a2.x); ffma2(acc2[2][1], f2p, a2.y);
            ffma2(acc2[3][0], f3, a2.x);  ffma2(acc2[3][1], f3, a2.y);
        }
#pragma unroll
        for (int i = 0; i < 4; i++) {
            const int d = d0 + ty * 4 + i;
#pragma unroll
            for (int p = 0; p < 2; p++) {
                float2 u = unpack2(acc2[i][p]);
                atomicAdd(&vb[d * 64 + tx * 4 + 2 * p],     u.x);
                atomicAdd(&vb[d * 64 + tx * 4 + 2 * p + 1], u.y);
            }
        }
    }
#undef XS
#undef CS
#undef SMM
#undef AT
#undef XS2
}

// ---------------- fold centers term + per-k sum of squares ----------------
// grid (16, 8): d-tile of 32, batch. block 256 = 64 k x 4 dy.
__global__ __launch_bounds__(256) void k_sumsq(const float* __restrict__ centers) {
    const int b = blockIdx.y;
    const int dt = blockIdx.x;
    const int k = threadIdx.x & 63;
    const int dy = threadIdx.x >> 6;
    float* vb = g_vlad + (size_t)b * 32768;
    const float A = g_asum[b * 64 + k];

    float ss = 0.0f;
#pragma unroll
    for (int m = 0; m < 8; m++) {
        const int d = dt * 32 + m * 4 + dy;
        const int i = d * 64 + k;
        float v = vb[i] - A * centers[i & 32767];  // centers[d*64+k]
        vb[i] = v;
        ss += v * v;
    }
    __shared__ float red[4][64];
    red[dy][k] = ss;
    __syncthreads();
    if (dy == 0) {
        float s = red[0][k] + red[1][k] + red[2][k] + red[3][k];
        atomicAdd(&g_ksum[b * 64 + k], s);
    }
}

// ---------------- compute combined scale + apply in place ----------------
// grid (16, 8): d-tile of 32, batch. block 256.
__global__ __launch_bounds__(256) void k_apply() {
    const int b = blockIdx.y;
    const int dt = blockIdx.x;
    const int t = threadIdx.x;
    const int k = t & 63;
    const int dy = t >> 6;

    __shared__ float sc_s[64];
    __shared__ float wred[2];

    float inv = 0.0f, contrib = 0.0f;
    if (t < 64) {
        float v = g_ksum[b * 64 + t];
        inv = 1.0f / fmaxf(sqrtf(v), EPSN);
        contrib = v * inv * inv;
    }
    float csum = contrib;
#pragma unroll
    for (int off = 16; off; off >>= 1) csum += __shfl_xor_sync(0xffffffffu, csum, off);
    if (t < 64 && (t & 31) == 0) wred[t >> 5] = csum;
    __syncthreads();
    if (t < 64) {
        float g = wred[0] + wred[1];
        sc_s[t] = inv * (1.0f / fmaxf(sqrtf(g), EPSN));
    }
    __syncthreads();

    float* vb = g_vlad + (size_t)b * 32768;
    const float sc = sc_s[k];
#pragma unroll
    for (int m = 0; m < 8; m++) {
        const int d = dt * 32 + m * 4 + dy;
        vb[d * 64 + k] *= sc;
    }
}

// ---------------- whitening GEMM: 64 rows/CTA, K-split 4, cp.async pipeline ----------------
// grid 256 = 64 rowtiles x 4 K-splits. block 256 (8 warps x 8 rows). dyn smem 72KB.
__global__ __launch_bounds__(256, 1) void k_whiten(const float* __restrict__ W) {
    extern __shared__ __align__(16) float smw[];
    // layout: W buffers [2][64*128] at 0, D buffers [2][8*128] at 16384 floats

    const int rowtile = blockIdx.x >> 2;
    const int ks = blockIdx.x & 3;
    const int o0 = rowtile * 64;
    const int jbase = ks * 8192;

    const int t = threadIdx.x;
    const int lane = t & 31;
    const int warp = t >> 5;
    const int r0 = warp * 8;
    const int c = lane * 4;
    const int wr = t >> 5;    // staging: warp stages rows wr*8..wr*8+7, batch wr
    const int wc4 = t & 31;

    ull acc[8][8];
#pragma unroll
    for (int r = 0; r < 8; r++)
#pragma unroll
        for (int bb = 0; bb < 8; bb++) acc[r][bb] = 0ULL;

    const uint32_t sbase = (uint32_t)__cvta_generic_to_shared(smw);

    auto stage = [&](int tile, int buf) {
        const int jc = jbase + tile * 128 + wc4 * 4;
        const float* Wg = W + (size_t)(o0 + wr * 8) * 32768 + jc;
#pragma unroll
        for (int i = 0; i < 8; i++)
            cpa16(sbase + (uint32_t)((buf * 8192 + (wr * 8 + i) * 128 + wc4 * 4) * 4),
                  Wg + (size_t)i * 32768);
        cpa16(sbase + (uint32_t)((16384 + buf * 1024 + wr * 128 + wc4 * 4) * 4),
              g_vlad + (size_t)wr * 32768 + jc);
        cpa_commit();
    };

    stage(0, 0);

    for (int tile = 0; tile < 64; tile++) {
        const int buf = tile & 1;
        if (tile < 63) {
            stage(tile + 1, buf ^ 1);
            asm volatile("cp.async.wait_group 1;");
        } else {
            asm volatile("cp.async.wait_group 0;");
        }
        __syncthreads();

        const float* Wt = smw + buf * 8192;
        const float* Dt = smw + 16384 + buf * 1024;
        ulonglong2 w2[8];
#pragma unroll
        for (int r = 0; r < 8; r++)
            w2[r] = *(const ulonglong2*)&Wt[(r0 + r) * 128 + c];
#pragma unroll
        for (int bb = 0; bb < 8; bb++) {
            ulonglong2 d2 = *(const ulonglong2*)&Dt[bb * 128 + c];
#pragma unroll
            for (int r = 0; r < 8; r++) {
                ffma2(acc[r][bb], w2[r].x, d2.x);
                ffma2(acc[r][bb], w2[r].y, d2.y);
            }
        }
        __syncthreads();
    }

    // collapse packed halves + warp butterfly reduce
    float accf[8][8];
#pragma unroll
    for (int r = 0; r < 8; r++)
#pragma unroll
        for (int bb = 0; bb < 8; bb++) {
            float2 f = unpack2(acc[r][bb]);
            float v = f.x + f.y;
#pragma unroll
            for (int off = 16; off; off >>= 1)
                v += __shfl_xor_sync(0xffffffffu, v, off);
            accf[r][bb] = v;
        }

    const int bsel = lane & 7;
#pragma unroll
    for (int half = 0; half < 2; half++) {
        const int rr = (lane >> 3) + half * 4;
        float res = 0.0f;
#pragma unroll
        for (int r = 0; r < 8; r++)
#pragma unroll
            for (int bb = 0; bb < 8; bb++)
                if (r == rr && bb == bsel) res = accf[r][bb];
        g_wpart[((size_t)ks * 8 + bsel) * 4096 + o0 + r0 + rr] = res;
    }
}

// ---------------- combine 4 K-partials + bias + final per-row L2 norm ----------------
__global__ __launch_bounds__(256) void k_final(const float* __restrict__ bias,
                                               float* __restrict__ out) {
    const int b = blockIdx.x;
    float v[16];
    float ss = 0.0f;
#pragma unroll
    for (int t = 0; t < 16; t++) {
        const int o = threadIdx.x + t * 256;
        float val = g_wpart[(size_t)b * 4096 + o]
                  + g_wpart[(size_t)(8 + b) * 4096 + o]
                  + g_wpart[(size_t)(16 + b) * 4096 + o]
                  + g_wpart[(size_t)(24 + b) * 4096 + o]
                  + bias[o];
        v[t] = val;
        ss += val * val;
    }
#pragma unroll
    for (int off = 16; off; off >>= 1) ss += __shfl_xor_sync(0xffffffffu, ss, off);
    __shared__ float r[8];
    __shared__ float sc;
    const int lane = threadIdx.x & 31, warp = threadIdx.x >> 5;
    if (lane == 0) r[warp] = ss;
    __syncthreads();
    if (threadIdx.x == 0) {
        float tt = 0.0f;
#pragma unroll
        for (int i = 0; i < 8; i++) tt += r[i];
        sc = 1.0f / fmaxf(sqrtf(tt), EPSN);
    }
    __syncthreads();
    float* ob = out + (size_t)b * 4096;
#pragma unroll
    for (int t = 0; t < 16; t++) ob[threadIdx.x + t * 256] = v[t] * sc;
}

// ---------------- launch ----------------
extern "C" void kernel_launch(void* const* d_in, const int* in_sizes, int n_in,
                              void* d_out, int out_size) {
    const float* x        = (const float*)d_in[0];
    const float* conv_w   = (const float*)d_in[1];
    const float* centers  = (const float*)d_in[2];
    const float* whiten_w = (const float*)d_in[3];
    const float* whiten_b = (const float*)d_in[4];
    float* out = (float*)d_out;

    static int attr_set = 0;
    if (!attr_set) {
        cudaFuncSetAttribute(k_whiten, cudaFuncAttributeMaxDynamicSharedMemorySize, 73728);
        attr_set = 1;
    }

    k_zero<<<1028, 256>>>();
    k_fused<<<dim3(25, 8), 256>>>(x, conv_w);
    k_sumsq<<<dim3(16, 8), 256>>>(centers);
    k_apply<<<dim3(16, 8), 256>>>();
    k_whiten<<<256, 256, 73728>>>(whiten_w);
    k_final<<<8, 256>>>(whiten_b, out);
}

// round 7
// speedup vs baseline: 1.9159x; 1.1072x over previous
#include <cuda_runtime.h>
#include <math.h>
#include <stdint.h>

// ---------------- scratch (device globals, no allocation) ----------------
__device__ float g_vpart[25 * 8 * 32768];  // [ntile][b][d*64+k] vlad partials
__device__ float g_vlad[8 * 32768];        // [b][d*64+k] centered -> scaled desc
__device__ float g_asum[8 * 64];           // [b][k] total assign sums
__device__ float g_ksum[8 * 64];           // [b][k] sum of squares over d
__device__ float g_wpart[2 * 8 * 4096];    // [ksplit][b][out] whiten partials

#define EPSN 1e-12f
typedef unsigned long long ull;

__device__ __forceinline__ void ffma2(ull& acc, ull a, ull b) {
    asm("fma.rn.f32x2 %0, %1, %2, %0;" : "+l"(acc) : "l"(a), "l"(b));
}
__device__ __forceinline__ ull pack2(float v) {
    ull r; asm("mov.b64 %0, {%1, %1};" : "=l"(r) : "f"(v)); return r;
}
__device__ __forceinline__ float2 unpack2(ull v) {
    float2 f; asm("mov.b64 {%0, %1}, %2;" : "=f"(f.x), "=f"(f.y) : "l"(v)); return f;
}
__device__ __forceinline__ void cpa16(uint32_t s, const void* g) {
    asm volatile("cp.async.cg.shared.global [%0], [%1], 16;" :: "r"(s), "l"(g));
}
__device__ __forceinline__ void cpa_commit() { asm volatile("cp.async.commit_group;"); }

// ---------------- zero small accumulators ----------------
__global__ void k_zero() {
    int i = threadIdx.x;
    if (i < 512) g_asum[i] = 0.0f;
    else g_ksum[i - 512] = 0.0f;
}

// ---------------- fused scores + softmax + vlad-gemm (partials, no atomics) ----------------
// grid (25, 8): n-tile of 64, batch. block 256 = 16x16. occ 2/SM -> single wave.
__global__ __launch_bounds__(256, 2) void k_fused(const float* __restrict__ x,
                                                  const float* __restrict__ cw) {
    const int b = blockIdx.y;
    const int n0 = blockIdx.x * 64;
    const int t = threadIdx.x;
    const int tx = t & 15;
    const int ty = t >> 4;

    __shared__ __align__(16) float u1[64 * 68];
    __shared__ __align__(16) float u2[64 * 68];
    __shared__ float inv_sum[64];
#define XS(r, c_)  u1[(r) * 68 + (c_)]
#define CS(r, c_)  u2[(r) * 68 + (c_)]
#define SMM(r, c_) u2[(r) * 68 + (c_)]
#define AT(r, c_)  u1[(r) * 68 + (c_)]
#define XS2(r, c_) u2[(r) * 68 + (c_)]

    const float* xb = x + (size_t)b * 512 * 1600;

    // ---- phase 1: scores = cw @ x_tile ----
    ull acc[4][2];
#pragma unroll
    for (int i = 0; i < 4; i++) { acc[i][0] = 0ULL; acc[i][1] = 0ULL; }

    for (int d0 = 0; d0 < 512; d0 += 64) {
        __syncthreads();
        for (int idx = t; idx < 4096; idx += 256) {
            int k = idx >> 6, dd = idx & 63;
            CS(dd, k) = cw[k * 512 + d0 + dd];
        }
        for (int idx = t; idx < 4096; idx += 256) {
            int dd = idx >> 6, nn = idx & 63;
            XS(dd, nn) = xb[(size_t)(d0 + dd) * 1600 + n0 + nn];
        }
        __syncthreads();
#pragma unroll 8
        for (int dd = 0; dd < 64; dd++) {
            float4 a = *(const float4*)&CS(dd, ty * 4);
            ulonglong2 f2 = *(const ulonglong2*)&XS(dd, tx * 4);
            ull a0 = pack2(a.x), a1 = pack2(a.y), a2 = pack2(a.z), a3 = pack2(a.w);
            ffma2(acc[0][0], a0, f2.x); ffma2(acc[0][1], a0, f2.y);
            ffma2(acc[1][0], a1, f2.x); ffma2(acc[1][1], a1, f2.y);
            ffma2(acc[2][0], a2, f2.x); ffma2(acc[2][1], a2, f2.y);
            ffma2(acc[3][0], a3, f2.x); ffma2(acc[3][1], a3, f2.y);
        }
    }
    __syncthreads();
#pragma unroll
    for (int i = 0; i < 4; i++)
#pragma unroll
        for (int p = 0; p < 2; p++) {
            float2 u = unpack2(acc[i][p]);
            SMM(ty * 4 + i, tx * 4 + 2 * p)     = u.x;
            SMM(ty * 4 + i, tx * 4 + 2 * p + 1) = u.y;
        }
    __syncthreads();

    // ---- softmax over k (per n column), normalize + per-k asum ----
    if (t < 64) {
        const int n = t;
        float mx = -1e30f;
#pragma unroll 8
        for (int k = 0; k < 64; k++) mx = fmaxf(mx, SMM(k, n));
        float s = 0.0f;
#pragma unroll 8
        for (int k = 0; k < 64; k++) {
            float e = __expf(SMM(k, n) - mx);
            SMM(k, n) = e;
            s += e;
        }
        inv_sum[n] = 1.0f / s;
    }
    __syncthreads();
    if (t < 64) {
        const int k = t;
        float s = 0.0f;
#pragma unroll 8
        for (int nn = 0; nn < 64; nn++) {
            float a = SMM(k, nn) * inv_sum[nn];
            SMM(k, nn) = a;
            s += a;
        }
        atomicAdd(&g_asum[b * 64 + k], s);
    }
    __syncthreads();
    // transpose assign into u1
    for (int idx = t; idx < 4096; idx += 256) {
        int k = idx >> 6, nn = idx & 63;
        AT(nn, k) = SMM(k, nn);
    }

    // ---- phase 2: vlad partial = x_tile @ assign^T -> STG float4 to g_vpart ----
    float* vp = g_vpart + ((size_t)blockIdx.x * 8 + b) * 32768;
    for (int d0 = 0; d0 < 512; d0 += 64) {
        __syncthreads();
        for (int idx = t; idx < 4096; idx += 256) {
            int dd = idx >> 6, nn = idx & 63;
            XS2(dd, nn) = xb[(size_t)(d0 + dd) * 1600 + n0 + nn];
        }
        __syncthreads();

        ull acc2[4][2];
#pragma unroll
        for (int i = 0; i < 4; i++) { acc2[i][0] = 0ULL; acc2[i][1] = 0ULL; }
#pragma unroll 4
        for (int nn = 0; nn < 64; nn++) {
            ulonglong2 a2 = *(const ulonglong2*)&AT(nn, tx * 4);
            ull f0 = pack2(XS2(ty * 4 + 0, nn));
            ull f1 = pack2(XS2(ty * 4 + 1, nn));
            ull f2p = pack2(XS2(ty * 4 + 2, nn));
            ull f3 = pack2(XS2(ty * 4 + 3, nn));
            ffma2(acc2[0][0], f0, a2.x);  ffma2(acc2[0][1], f0, a2.y);
            ffma2(acc2[1][0], f1, a2.x);  ffma2(acc2[1][1], f1, a2.y);
            ffma2(acc2[2][0], f2p, a2.x); ffma2(acc2[2][1], f2p, a2.y);
            ffma2(acc2[3][0], f3, a2.x);  ffma2(acc2[3][1], f3, a2.y);
        }
#pragma unroll
        for (int i = 0; i < 4; i++) {
            const int d = d0 + ty * 4 + i;
            float2 lo = unpack2(acc2[i][0]);
            float2 hi = unpack2(acc2[i][1]);
            float4 o; o.x = lo.x; o.y = lo.y; o.z = hi.x; o.w = hi.y;
            *(float4*)&vp[d * 64 + tx * 4] = o;
        }
    }
#undef XS
#undef CS
#undef SMM
#undef AT
#undef XS2
}

// ---------------- sum 25 partials + centers fold + per-k sum of squares ----------------
// grid (16, 8): d-tile of 32, batch. block 256.
__global__ __launch_bounds__(256) void k_sumsq(const float* __restrict__ centers) {
    const int b = blockIdx.y;
    const int dt = blockIdx.x;
    const int t = threadIdx.x;
    const int tx = t & 15;   // k-group (float4)
    const int ty = t >> 4;   // d sub-row

    const float4* c4p = (const float4*)centers;
    const float4* A4p = (const float4*)(g_asum + b * 64);
    float4* vlad4 = (float4*)(g_vlad + (size_t)b * 32768);

    float4 ss4 = make_float4(0.f, 0.f, 0.f, 0.f);
    const float4 A4 = A4p[tx];

#pragma unroll
    for (int h = 0; h < 2; h++) {
        const int d = dt * 32 + ty + h * 16;
        const int i4 = d * 16 + tx;   // float4 index within batch
        float4 v = make_float4(0.f, 0.f, 0.f, 0.f);
#pragma unroll
        for (int s = 0; s < 25; s++) {
            float4 p = *(const float4*)(g_vpart + ((size_t)s * 8 + b) * 32768 + i4 * 4);
            v.x += p.x; v.y += p.y; v.z += p.z; v.w += p.w;
        }
        float4 c = c4p[i4 & 8191];
        v.x -= A4.x * c.x; v.y -= A4.y * c.y; v.z -= A4.z * c.z; v.w -= A4.w * c.w;
        vlad4[i4] = v;
        ss4.x += v.x * v.x; ss4.y += v.y * v.y; ss4.z += v.z * v.z; ss4.w += v.w * v.w;
    }

    __shared__ __align__(16) float red[16][68];
    *(float4*)&red[ty][tx * 4] = ss4;
    __syncthreads();
    if (t < 64) {
        float s = 0.0f;
#pragma unroll
        for (int r = 0; r < 16; r++) s += red[r][t];
        atomicAdd(&g_ksum[b * 64 + t], s);
    }
}

// ---------------- compute combined scale + apply in place ----------------
// grid (16, 8): d-tile of 32, batch. block 256.
__global__ __launch_bounds__(256) void k_apply() {
    const int b = blockIdx.y;
    const int dt = blockIdx.x;
    const int t = threadIdx.x;
    const int k = t & 63;
    const int dy = t >> 6;

    __shared__ float sc_s[64];
    __shared__ float wred[2];

    float inv = 0.0f, contrib = 0.0f;
    if (t < 64) {
        float v = g_ksum[b * 64 + t];
        inv = 1.0f / fmaxf(sqrtf(v), EPSN);
        contrib = v * inv * inv;
    }
    float csum = contrib;
#pragma unroll
    for (int off = 16; off; off >>= 1) csum += __shfl_xor_sync(0xffffffffu, csum, off);
    if (t < 64 && (t & 31) == 0) wred[t >> 5] = csum;
    __syncthreads();
    if (t < 64) {
        float g = wred[0] + wred[1];
        sc_s[t] = inv * (1.0f / fmaxf(sqrtf(g), EPSN));
    }
    __syncthreads();

    float* vb = g_vlad + (size_t)b * 32768;
    const float sc = sc_s[k];
#pragma unroll
    for (int m = 0; m < 8; m++) {
        const int d = dt * 32 + m * 4 + dy;
        vb[d * 64 + k] *= sc;
    }
}

// ---------------- whitening GEMM: 32 rows/CTA, K-split 2, 4-stage cp.async ----------------
// grid 256 = 128 rowtiles x 2 K-halves. block 256 (8 warps x 4 rows). 80KB dyn smem, occ 2.
__global__ __launch_bounds__(256, 2) void k_whiten(const float* __restrict__ W) {
    extern __shared__ __align__(16) float smw[];
    // W stages: [4][32*128] floats at offset 0 (16384 floats)
    // D stages: [4][8*128]  floats at offset 16384 (4096 floats)

    const int rowtile = blockIdx.x >> 1;
    const int ks = blockIdx.x & 1;
    const int o0 = rowtile * 32;
    const int jbase = ks * 16384;

    const int t = threadIdx.x;
    const int lane = t & 31;
    const int warp = t >> 5;
    const int r0 = warp * 4;
    const int c = lane * 4;
    const int wr = t >> 5;     // staging warp id
    const int wc4 = t & 31;    // staging float4 column

    ull acc[4][8];
#pragma unroll
    for (int r = 0; r < 4; r++)
#pragma unroll
        for (int bb = 0; bb < 8; bb++) acc[r][bb] = 0ULL;

    const uint32_t sbase = (uint32_t)__cvta_generic_to_shared(smw);
    const float* Wbase = W + (size_t)o0 * 32768 + jbase;
    const float* Dbase = g_vlad + jbase;

    auto stage = [&](int tile, int buf) {
        const int jc = tile * 128 + wc4 * 4;
#pragma unroll
        for (int i = 0; i < 4; i++) {
            const int r = wr + i * 8;
            cpa16(sbase + (uint32_t)((buf * 4096 + r * 128 + wc4 * 4) * 4),
                  Wbase + (size_t)r * 32768 + jc);
        }
        cpa16(sbase + (uint32_t)((16384 + buf * 1024 + wr * 128 + wc4 * 4) * 4),
              Dbase + (size_t)wr * 32768 + jc);
        cpa_commit();
    };

    stage(0, 0); stage(1, 1); stage(2, 2);

    const int T = 128;
    for (int tile = 0; tile < T; tile++) {
        const int buf = tile & 3;
        if (tile + 3 < T) {
            stage(tile + 3, (tile + 3) & 3);
            asm volatile("cp.async.wait_group 3;");
        } else if (tile + 2 < T) {
            asm volatile("cp.async.wait_group 2;");
        } else if (tile + 1 < T) {
            asm volatile("cp.async.wait_group 1;");
        } else {
            asm volatile("cp.async.wait_group 0;");
        }
        __syncthreads();

        const float* Wt = smw + buf * 4096;
        const float* Dt = smw + 16384 + buf * 1024;
        ulonglong2 w2[4];
#pragma unroll
        for (int r = 0; r < 4; r++)
            w2[r] = *(const ulonglong2*)&Wt[(r0 + r) * 128 + c];
#pragma unroll
        for (int bb = 0; bb < 8; bb++) {
            ulonglong2 d2 = *(const ulonglong2*)&Dt[bb * 128 + c];
#pragma unroll
            for (int r = 0; r < 4; r++) {
                ffma2(acc[r][bb], w2[r].x, d2.x);
                ffma2(acc[r][bb], w2[r].y, d2.y);
            }
        }
        __syncthreads();
    }

    // collapse packed halves + warp butterfly reduce
    float accf[4][8];
#pragma unroll
    for (int r = 0; r < 4; r++)
#pragma unroll
        for (int bb = 0; bb < 8; bb++) {
            float2 f = unpack2(acc[r][bb]);
            float v = f.x + f.y;
#pragma unroll
            for (int off = 16; off; off >>= 1)
                v += __shfl_xor_sync(0xffffffffu, v, off);
            accf[r][bb] = v;
        }

    const int rr = lane >> 3;
    const int bsel = lane & 7;
    float res = 0.0f;
#pragma unroll
    for (int r = 0; r < 4; r++)
#pragma unroll
        for (int bb = 0; bb < 8; bb++)
            if (r == rr && bb == bsel) res = accf[r][bb];

    g_wpart[((size_t)ks * 8 + bsel) * 4096 + o0 + r0 + rr] = res;
}

// ---------------- combine 2 K-partials + bias + final per-row L2 norm ----------------
__global__ __launch_bounds__(256) void k_final(const float* __restrict__ bias,
                                               float* __restrict__ out) {
    const int b = blockIdx.x;
    float v[16];
    float ss = 0.0f;
#pragma unroll
    for (int t = 0; t < 16; t++) {
        const int o = threadIdx.x + t * 256;
        float val = g_wpart[(size_t)b * 4096 + o]
                  + g_wpart[(size_t)(8 + b) * 4096 + o]
                  + bias[o];
        v[t] = val;
        ss += val * val;
    }
#pragma unroll
    for (int off = 16; off; off >>= 1) ss += __shfl_xor_sync(0xffffffffu, ss, off);
    __shared__ float r[8];
    __shared__ float sc;
    const int lane = threadIdx.x & 31, warp = threadIdx.x >> 5;
    if (lane == 0) r[warp] = ss;
    __syncthreads();
    if (threadIdx.x == 0) {
        float tt = 0.0f;
#pragma unroll
        for (int i = 0; i < 8; i++) tt += r[i];
        sc = 1.0f / fmaxf(sqrtf(tt), EPSN);
    }
    __syncthreads();
    float* ob = out + (size_t)b * 4096;
#pragma unroll
    for (int t = 0; t < 16; t++) ob[threadIdx.x + t * 256] = v[t] * sc;
}

// ---------------- launch ----------------
extern "C" void kernel_launch(void* const* d_in, const int* in_sizes, int n_in,
                              void* d_out, int out_size) {
    const float* x        = (const float*)d_in[0];
    const float* conv_w   = (const float*)d_in[1];
    const float* centers  = (const float*)d_in[2];
    const float* whiten_w = (const float*)d_in[3];
    const float* whiten_b = (const float*)d_in[4];
    float* out = (float*)d_out;

    static int attr_set = 0;
    if (!attr_set) {
        cudaFuncSetAttribute(k_whiten, cudaFuncAttributeMaxDynamicSharedMemorySize, 81920);
        attr_set = 1;
    }

    k_zero<<<1, 1024>>>();
    k_fused<<<dim3(25, 8), 256>>>(x, conv_w);
    k_sumsq<<<dim3(16, 8), 256>>>(centers);
    k_apply<<<dim3(16, 8), 256>>>();
    k_whiten<<<256, 256, 81920>>>(whiten_w);
    k_final<<<8, 256>>>(whiten_b, out);
}

// round 8
// speedup vs baseline: 2.1791x; 1.1374x over previous
#include <cuda_runtime.h>
#include <math.h>
#include <stdint.h>

// ---------------- scratch (device globals, no allocation) ----------------
__device__ float g_cwT[512 * 64];          // conv_w transposed [d][k]
__device__ float g_vpart[25 * 8 * 32768];  // [ntile][b][d*64+k] vlad partials
__device__ float g_vlad[8 * 32768];        // [b][d*64+k] centered -> scaled desc
__device__ float g_asum[8 * 64];           // [b][k] total assign sums
__device__ float g_ksum[8 * 64];           // [b][k] sum of squares over d
__device__ float g_wpart[2 * 8 * 4096];    // [ksplit][b][out] whiten partials

#define EPSN 1e-12f
typedef unsigned long long ull;

__device__ __forceinline__ void ffma2(ull& acc, ull a, ull b) {
    asm("fma.rn.f32x2 %0, %1, %2, %0;" : "+l"(acc) : "l"(a), "l"(b));
}
__device__ __forceinline__ ull pack2(float v) {
    ull r; asm("mov.b64 %0, {%1, %1};" : "=l"(r) : "f"(v)); return r;
}
__device__ __forceinline__ float2 unpack2(ull v) {
    float2 f; asm("mov.b64 {%0, %1}, %2;" : "=f"(f.x), "=f"(f.y) : "l"(v)); return f;
}
__device__ __forceinline__ void cpa16(uint32_t s, const void* g) {
    asm volatile("cp.async.cg.shared.global [%0], [%1], 16;" :: "r"(s), "l"(g));
}
__device__ __forceinline__ void cpa_commit() { asm volatile("cp.async.commit_group;"); }

// ---------------- prep: transpose conv_w + zero accumulators ----------------
__global__ void k_prep(const float* __restrict__ cw) {
    const int k = blockIdx.x;
    const int d = threadIdx.x;
    g_cwT[d * 64 + k] = cw[k * 512 + d];
    if (blockIdx.x == 0) { g_asum[d & 511] = 0.0f; g_ksum[d & 511] = 0.0f; }
}

// ---------------- fused scores + softmax + vlad-gemm (cp.async pipelined) ----------------
// grid (25, 8): n-tile of 64, batch. block 256 = 16x16. 85KB dyn smem, occ 2.
__global__ __launch_bounds__(256, 2) void k_fused(const float* __restrict__ x) {
    extern __shared__ __align__(16) float smf[];
    // 5 buffers of 4352 floats (64 rows x 68 pad) + inv_sum
    float* XB0 = smf;
    float* XB1 = smf + 4352;
    float* CB0 = smf + 8704;
    float* CB1 = smf + 13056;
    float* SC  = smf + 17408;          // scores [k][n] then assignT [n][k]
    float* inv_sum = smf + 21760;      // 64 floats

    const int b = blockIdx.y;
    const int n0 = blockIdx.x * 64;
    const int t = threadIdx.x;
    const int tx = t & 15;
    const int ty = t >> 4;

    const float* xb = x + (size_t)b * 512 * 1600;

    const uint32_t sx0 = (uint32_t)__cvta_generic_to_shared(XB0);
    const uint32_t sx1 = (uint32_t)__cvta_generic_to_shared(XB1);
    const uint32_t sc0 = (uint32_t)__cvta_generic_to_shared(CB0);
    const uint32_t sc1 = (uint32_t)__cvta_generic_to_shared(CB1);
    const int qdd = t >> 4;            // staging row sub-id
    const int qn4 = t & 15;            // staging 16B chunk within row

    // ---- phase 1: scores = cw @ x_tile, pipelined over 8 d-tiles of 64 ----
    auto stage1 = [&](int tile, int buf) {
        const int d0 = tile * 64;
        const uint32_t bx = buf ? sx1 : sx0;
        const uint32_t bc = buf ? sc1 : sc0;
#pragma unroll
        for (int i = 0; i < 4; i++) {
            const int dd = qdd + i * 16;
            cpa16(bx + (uint32_t)((dd * 68 + qn4 * 4) * 4),
                  xb + (size_t)(d0 + dd) * 1600 + n0 + qn4 * 4);
            cpa16(bc + (uint32_t)((dd * 68 + qn4 * 4) * 4),
                  g_cwT + (d0 + dd) * 64 + qn4 * 4);
        }
        cpa_commit();
    };

    ull acc[4][2];
#pragma unroll
    for (int i = 0; i < 4; i++) { acc[i][0] = 0ULL; acc[i][1] = 0ULL; }

    stage1(0, 0);
    for (int tile = 0; tile < 8; tile++) {
        const int buf = tile & 1;
        if (tile < 7) {
            stage1(tile + 1, buf ^ 1);
            asm volatile("cp.async.wait_group 1;");
        } else {
            asm volatile("cp.async.wait_group 0;");
        }
        __syncthreads();

        const float* CS = buf ? CB1 : CB0;
        const float* XS = buf ? XB1 : XB0;
#pragma unroll 8
        for (int dd = 0; dd < 64; dd++) {
            float4 a = *(const float4*)&CS[dd * 68 + ty * 4];
            ulonglong2 f2 = *(const ulonglong2*)&XS[dd * 68 + tx * 4];
            ull a0 = pack2(a.x), a1 = pack2(a.y), a2 = pack2(a.z), a3 = pack2(a.w);
            ffma2(acc[0][0], a0, f2.x); ffma2(acc[0][1], a0, f2.y);
            ffma2(acc[1][0], a1, f2.x); ffma2(acc[1][1], a1, f2.y);
            ffma2(acc[2][0], a2, f2.x); ffma2(acc[2][1], a2, f2.y);
            ffma2(acc[3][0], a3, f2.x); ffma2(acc[3][1], a3, f2.y);
        }
        __syncthreads();
    }

    // scores -> SC [k][n]
#pragma unroll
    for (int i = 0; i < 4; i++)
#pragma unroll
        for (int p = 0; p < 2; p++) {
            float2 u = unpack2(acc[i][p]);
            SC[(ty * 4 + i) * 68 + tx * 4 + 2 * p]     = u.x;
            SC[(ty * 4 + i) * 68 + tx * 4 + 2 * p + 1] = u.y;
        }
    __syncthreads();

    // softmax over k (per n column)
    if (t < 64) {
        const int n = t;
        float mx = -1e30f;
#pragma unroll 8
        for (int k = 0; k < 64; k++) mx = fmaxf(mx, SC[k * 68 + n]);
        float s = 0.0f;
#pragma unroll 8
        for (int k = 0; k < 64; k++) {
            float e = __expf(SC[k * 68 + n] - mx);
            SC[k * 68 + n] = e;
            s += e;
        }
        inv_sum[n] = 1.0f / s;
    }
    __syncthreads();
    // normalize rows + per-k asum
    if (t < 64) {
        const int k = t;
        float s = 0.0f;
#pragma unroll 8
        for (int nn = 0; nn < 64; nn++) {
            float a = SC[k * 68 + nn] * inv_sum[nn];
            SC[k * 68 + nn] = a;
            s += a;
        }
        atomicAdd(&g_asum[b * 64 + k], s);
    }
    __syncthreads();
    // in-place transpose SC: [k][n] -> [n][k] via registers
    {
        float tmp[16];
#pragma unroll
        for (int i = 0; i < 16; i++) {
            const int idx = t + i * 256;
            tmp[i] = SC[(idx >> 6) * 68 + (idx & 63)];
        }
        __syncthreads();
#pragma unroll
        for (int i = 0; i < 16; i++) {
            const int idx = t + i * 256;
            SC[(idx & 63) * 68 + (idx >> 6)] = tmp[i];
        }
    }

    // ---- phase 2: vlad partial = x_tile @ assign^T, pipelined; STG to g_vpart ----
    auto stage2 = [&](int tile, int buf) {
        const int d0 = tile * 64;
        const uint32_t bx = buf ? sx1 : sx0;
#pragma unroll
        for (int i = 0; i < 4; i++) {
            const int dd = qdd + i * 16;
            cpa16(bx + (uint32_t)((dd * 68 + qn4 * 4) * 4),
                  xb + (size_t)(d0 + dd) * 1600 + n0 + qn4 * 4);
        }
        cpa_commit();
    };

    float* vp = g_vpart + ((size_t)blockIdx.x * 8 + b) * 32768;
    __syncthreads();
    stage2(0, 0);
    for (int tile = 0; tile < 8; tile++) {
        const int buf = tile & 1;
        if (tile < 7) {
            stage2(tile + 1, buf ^ 1);
            asm volatile("cp.async.wait_group 1;");
        } else {
            asm volatile("cp.async.wait_group 0;");
        }
        __syncthreads();

        const float* XS2 = buf ? XB1 : XB0;
        ull acc2[4][2];
#pragma unroll
        for (int i = 0; i < 4; i++) { acc2[i][0] = 0ULL; acc2[i][1] = 0ULL; }
#pragma unroll 4
        for (int nn = 0; nn < 64; nn++) {
            ulonglong2 a2 = *(const ulonglong2*)&SC[nn * 68 + tx * 4];
            ull f0 = pack2(XS2[(ty * 4 + 0) * 68 + nn]);
            ull f1 = pack2(XS2[(ty * 4 + 1) * 68 + nn]);
            ull f2p = pack2(XS2[(ty * 4 + 2) * 68 + nn]);
            ull f3 = pack2(XS2[(ty * 4 + 3) * 68 + nn]);
            ffma2(acc2[0][0], f0, a2.x);  ffma2(acc2[0][1], f0, a2.y);
            ffma2(acc2[1][0], f1, a2.x);  ffma2(acc2[1][1], f1, a2.y);
            ffma2(acc2[2][0], f2p, a2.x); ffma2(acc2[2][1], f2p, a2.y);
            ffma2(acc2[3][0], f3, a2.x);  ffma2(acc2[3][1], f3, a2.y);
        }
        const int d0 = tile * 64;
#pragma unroll
        for (int i = 0; i < 4; i++) {
            const int d = d0 + ty * 4 + i;
            float2 lo = unpack2(acc2[i][0]);
            float2 hi = unpack2(acc2[i][1]);
            float4 o; o.x = lo.x; o.y = lo.y; o.z = hi.x; o.w = hi.y;
            *(float4*)&vp[d * 64 + tx * 4] = o;
        }
        __syncthreads();
    }
}

// ---------------- sum 25 partials + centers fold + per-k sum of squares ----------------
// grid (32, 8): d-tile of 16, batch. block 256; one float4 per thread.
__global__ __launch_bounds__(256) void k_sumsq(const float* __restrict__ centers) {
    const int b = blockIdx.y;
    const int t = threadIdx.x;
    const int i4 = blockIdx.x * 256 + t;   // float4 index within batch (0..8191)
    const int q = t & 15;                  // k4 group: k = q*4..q*4+3

    const float4* c4p = (const float4*)centers;
    const float4* A4p = (const float4*)(g_asum + b * 64);

    float4 v = make_float4(0.f, 0.f, 0.f, 0.f);
#pragma unroll
    for (int s = 0; s < 25; s++) {
        float4 p = *(const float4*)(g_vpart + ((size_t)s * 8 + b) * 32768 + (size_t)i4 * 4);
        v.x += p.x; v.y += p.y; v.z += p.z; v.w += p.w;
    }
    const float4 A4 = A4p[q];
    const float4 c = c4p[i4];
    v.x -= A4.x * c.x; v.y -= A4.y * c.y; v.z -= A4.z * c.z; v.w -= A4.w * c.w;
    ((float4*)(g_vlad + (size_t)b * 32768))[i4] = v;

    __shared__ __align__(16) float4 red[256];
    red[t] = make_float4(v.x * v.x, v.y * v.y, v.z * v.z, v.w * v.w);
    __syncthreads();
    if (t < 16) {
        float4 s = make_float4(0.f, 0.f, 0.f, 0.f);
#pragma unroll
        for (int j = 0; j < 16; j++) {
            float4 r = red[t + j * 16];
            s.x += r.x; s.y += r.y; s.z += r.z; s.w += r.w;
        }
        atomicAdd(&g_ksum[b * 64 + t * 4 + 0], s.x);
        atomicAdd(&g_ksum[b * 64 + t * 4 + 1], s.y);
        atomicAdd(&g_ksum[b * 64 + t * 4 + 2], s.z);
        atomicAdd(&g_ksum[b * 64 + t * 4 + 3], s.w);
    }
}

// ---------------- compute combined scale + apply in place ----------------
// grid (32, 8). block 256; one float4 per thread.
__global__ __launch_bounds__(256) void k_apply() {
    const int b = blockIdx.y;
    const int t = threadIdx.x;

    __shared__ float sc_s[64];
    __shared__ float wred[2];

    float inv = 0.0f, contrib = 0.0f;
    if (t < 64) {
        float v = g_ksum[b * 64 + t];
        inv = 1.0f / fmaxf(sqrtf(v), EPSN);
        contrib = v * inv * inv;
    }
    float csum = contrib;
#pragma unroll
    for (int off = 16; off; off >>= 1) csum += __shfl_xor_sync(0xffffffffu, csum, off);
    if (t < 64 && (t & 31) == 0) wred[t >> 5] = csum;
    __syncthreads();
    if (t < 64) {
        float g = wred[0] + wred[1];
        sc_s[t] = inv * (1.0f / fmaxf(sqrtf(g), EPSN));
    }
    __syncthreads();

    const int i4 = blockIdx.x * 256 + t;
    const int q = t & 15;
    float4 sc4 = *(const float4*)&sc_s[q * 4];
    float4* vp = (float4*)(g_vlad + (size_t)b * 32768);
    float4 v = vp[i4];
    v.x *= sc4.x; v.y *= sc4.y; v.z *= sc4.z; v.w *= sc4.w;
    vp[i4] = v;
}

// ---------------- whitening GEMM: 32 rows/CTA, K-split 2, 4-stage cp.async ----------------
// grid 256 = 128 rowtiles x 2 K-halves. block 256 (8 warps x 4 rows). 80KB dyn smem, occ 2.
__global__ __launch_bounds__(256, 2) void k_whiten(const float* __restrict__ W) {
    extern __shared__ __align__(16) float smw[];

    const int rowtile = blockIdx.x >> 1;
    const int ks = blockIdx.x & 1;
    const int o0 = rowtile * 32;
    const int jbase = ks * 16384;

    const int t = threadIdx.x;
    const int lane = t & 31;
    const int warp = t >> 5;
    const int r0 = warp * 4;
    const int c = lane * 4;
    const int wr = t >> 5;
    const int wc4 = t & 31;

    ull acc[4][8];
#pragma unroll
    for (int r = 0; r < 4; r++)
#pragma unroll
        for (int bb = 0; bb < 8; bb++) acc[r][bb] = 0ULL;

    const uint32_t sbase = (uint32_t)__cvta_generic_to_shared(smw);
    const float* Wbase = W + (size_t)o0 * 32768 + jbase;
    const float* Dbase = g_vlad + jbase;

    auto stage = [&](int tile, int buf) {
        const int jc = tile * 128 + wc4 * 4;
#pragma unroll
        for (int i = 0; i < 4; i++) {
            const int r = wr + i * 8;
            cpa16(sbase + (uint32_t)((buf * 4096 + r * 128 + wc4 * 4) * 4),
                  Wbase + (size_t)r * 32768 + jc);
        }
        cpa16(sbase + (uint32_t)((16384 + buf * 1024 + wr * 128 + wc4 * 4) * 4),
              Dbase + (size_t)wr * 32768 + jc);
        cpa_commit();
    };

    stage(0, 0); stage(1, 1); stage(2, 2);

    const int T = 128;
    for (int tile = 0; tile < T; tile++) {
        const int buf = tile & 3;
        if (tile + 3 < T) {
            stage(tile + 3, (tile + 3) & 3);
            asm volatile("cp.async.wait_group 3;");
        } else if (tile + 2 < T) {
            asm volatile("cp.async.wait_group 2;");
        } else if (tile + 1 < T) {
            asm volatile("cp.async.wait_group 1;");
        } else {
            asm volatile("cp.async.wait_group 0;");
        }
        __syncthreads();

        const float* Wt = smw + buf * 4096;
        const float* Dt = smw + 16384 + buf * 1024;
        ulonglong2 w2[4];
#pragma unroll
        for (int r = 0; r < 4; r++)
            w2[r] = *(const ulonglong2*)&Wt[(r0 + r) * 128 + c];
#pragma unroll
        for (int bb = 0; bb < 8; bb++) {
            ulonglong2 d2 = *(const ulonglong2*)&Dt[bb * 128 + c];
#pragma unroll
            for (int r = 0; r < 4; r++) {
                ffma2(acc[r][bb], w2[r].x, d2.x);
                ffma2(acc[r][bb], w2[r].y, d2.y);
            }
        }
        __syncthreads();
    }

    float accf[4][8];
#pragma unroll
    for (int r = 0; r < 4; r++)
#pragma unroll
        for (int bb = 0; bb < 8; bb++) {
            float2 f = unpack2(acc[r][bb]);
            float v = f.x + f.y;
#pragma unroll
            for (int off = 16; off; off >>= 1)
                v += __shfl_xor_sync(0xffffffffu, v, off);
            accf[r][bb] = v;
        }

    const int rr = lane >> 3;
    const int bsel = lane & 7;
    float res = 0.0f;
#pragma unroll
    for (int r = 0; r < 4; r++)
#pragma unroll
        for (int bb = 0; bb < 8; bb++)
            if (r == rr && bb == bsel) res = accf[r][bb];

    g_wpart[((size_t)ks * 8 + bsel) * 4096 + o0 + r0 + rr] = res;
}

// ---------------- combine 2 K-partials + bias + final per-row L2 norm ----------------
__global__ __launch_bounds__(256) void k_final(const float* __restrict__ bias,
                                               float* __restrict__ out) {
    const int b = blockIdx.x;
    float v[16];
    float ss = 0.0f;
#pragma unroll
    for (int t = 0; t < 16; t++) {
        const int o = threadIdx.x + t * 256;
        float val = g_wpart[(size_t)b * 4096 + o]
                  + g_wpart[(size_t)(8 + b) * 4096 + o]
                  + bias[o];
        v[t] = val;
        ss += val * val;
    }
#pragma unroll
    for (int off = 16; off; off >>= 1) ss += __shfl_xor_sync(0xffffffffu, ss, off);
    __shared__ float r[8];
    __shared__ float sc;
    const int lane = threadIdx.x & 31, warp = threadIdx.x >> 5;
    if (lane == 0) r[warp] = ss;
    __syncthreads();
    if (threadIdx.x == 0) {
        float tt = 0.0f;
#pragma unroll
        for (int i = 0; i < 8; i++) tt += r[i];
        sc = 1.0f / fmaxf(sqrtf(tt), EPSN);
    }
    __syncthreads();
    float* ob = out + (size_t)b * 4096;
#pragma unroll
    for (int t = 0; t < 16; t++) ob[threadIdx.x + t * 256] = v[t] * sc;
}

// ---------------- launch ----------------
extern "C" void kernel_launch(void* const* d_in, const int* in_sizes, int n_in,
                              void* d_out, int out_size) {
    const float* x        = (const float*)d_in[0];
    const float* conv_w   = (const float*)d_in[1];
    const float* centers  = (const float*)d_in[2];
    const float* whiten_w = (const float*)d_in[3];
    const float* whiten_b = (const float*)d_in[4];
    float* out = (float*)d_out;

    static int attr_set = 0;
    if (!attr_set) {
        cudaFuncSetAttribute(k_whiten, cudaFuncAttributeMaxDynamicSharedMemorySize, 81920);
        cudaFuncSetAttribute(k_fused, cudaFuncAttributeMaxDynamicSharedMemorySize, 87296);
        attr_set = 1;
    }

    k_prep<<<64, 512>>>(conv_w);
    k_fused<<<dim3(25, 8), 256, 87296>>>(x);
    k_sumsq<<<dim3(32, 8), 256>>>(centers);
    k_apply<<<dim3(32, 8), 256>>>();
    k_whiten<<<256, 256, 81920>>>(whiten_w);
    k_final<<<8, 256>>>(whiten_b, out);
}

// round 9
// speedup vs baseline: 2.2096x; 1.0140x over previous
#include <cuda_runtime.h>
#include <math.h>
#include <stdint.h>

// ---------------- scratch (device globals, no allocation) ----------------
__device__ float g_cwT[512 * 64];          // conv_w transposed [d][k]
__device__ float g_vpart[25 * 8 * 32768];  // [ntile][b][d*64+k] vlad partials
__device__ float g_vlad[8 * 32768];        // [b][d*64+k] centered + scaled desc
__device__ float g_asum[8 * 64];           // [b][k] total assign sums
__device__ float g_ksum[8 * 64];           // [b][k] sum of squares over d
__device__ unsigned g_cntb[8];             // per-batch block-completion counters
__device__ float g_wpart[2 * 8 * 4096];    // [ksplit][b][out] whiten partials

#define EPSN 1e-12f
typedef unsigned long long ull;

__device__ __forceinline__ void ffma2(ull& acc, ull a, ull b) {
    asm("fma.rn.f32x2 %0, %1, %2, %0;" : "+l"(acc) : "l"(a), "l"(b));
}
__device__ __forceinline__ ull pack2(float v) {
    ull r; asm("mov.b64 %0, {%1, %1};" : "=l"(r) : "f"(v)); return r;
}
__device__ __forceinline__ float2 unpack2(ull v) {
    float2 f; asm("mov.b64 {%0, %1}, %2;" : "=f"(f.x), "=f"(f.y) : "l"(v)); return f;
}
__device__ __forceinline__ void cpa16(uint32_t s, const void* g) {
    asm volatile("cp.async.cg.shared.global [%0], [%1], 16;" :: "r"(s), "l"(g));
}
__device__ __forceinline__ void cpa_commit() { asm volatile("cp.async.commit_group;"); }

// ---------------- prep: transpose conv_w + zero accumulators + reset counters ----------------
__global__ void k_prep(const float* __restrict__ cw) {
    const int k = blockIdx.x;
    const int d = threadIdx.x;
    g_cwT[d * 64 + k] = cw[k * 512 + d];
    if (blockIdx.x == 0) {
        g_asum[d & 511] = 0.0f;
        g_ksum[d & 511] = 0.0f;
        if (d < 8) g_cntb[d] = 0u;
    }
}

// ---------------- fused scores + softmax + vlad-gemm (cp.async pipelined) ----------------
// grid (25, 8): n-tile of 64, batch. block 256 = 16x16. 85KB dyn smem, occ 2.
__global__ __launch_bounds__(256, 2) void k_fused(const float* __restrict__ x) {
    extern __shared__ __align__(16) float smf[];
    float* XB0 = smf;
    float* XB1 = smf + 4352;
    float* CB0 = smf + 8704;
    float* CB1 = smf + 13056;
    float* SC  = smf + 17408;          // scores [k][n] then assignT [n][k]
    float* inv_sum = smf + 21760;      // 64 floats

    const int b = blockIdx.y;
    const int n0 = blockIdx.x * 64;
    const int t = threadIdx.x;
    const int tx = t & 15;
    const int ty = t >> 4;

    const float* xb = x + (size_t)b * 512 * 1600;

    const uint32_t sx0 = (uint32_t)__cvta_generic_to_shared(XB0);
    const uint32_t sx1 = (uint32_t)__cvta_generic_to_shared(XB1);
    const uint32_t sc0 = (uint32_t)__cvta_generic_to_shared(CB0);
    const uint32_t sc1 = (uint32_t)__cvta_generic_to_shared(CB1);
    const int qdd = t >> 4;
    const int qn4 = t & 15;

    auto stage1 = [&](int tile, int buf) {
        const int d0 = tile * 64;
        const uint32_t bx = buf ? sx1 : sx0;
        const uint32_t bc = buf ? sc1 : sc0;
#pragma unroll
        for (int i = 0; i < 4; i++) {
            const int dd = qdd + i * 16;
            cpa16(bx + (uint32_t)((dd * 68 + qn4 * 4) * 4),
                  xb + (size_t)(d0 + dd) * 1600 + n0 + qn4 * 4);
            cpa16(bc + (uint32_t)((dd * 68 + qn4 * 4) * 4),
                  g_cwT + (d0 + dd) * 64 + qn4 * 4);
        }
        cpa_commit();
    };

    ull acc[4][2];
#pragma unroll
    for (int i = 0; i < 4; i++) { acc[i][0] = 0ULL; acc[i][1] = 0ULL; }

    stage1(0, 0);
    for (int tile = 0; tile < 8; tile++) {
        const int buf = tile & 1;
        if (tile < 7) {
            stage1(tile + 1, buf ^ 1);
            asm volatile("cp.async.wait_group 1;");
        } else {
            asm volatile("cp.async.wait_group 0;");
        }
        __syncthreads();

        const float* CS = buf ? CB1 : CB0;
        const float* XS = buf ? XB1 : XB0;
#pragma unroll 8
        for (int dd = 0; dd < 64; dd++) {
            float4 a = *(const float4*)&CS[dd * 68 + ty * 4];
            ulonglong2 f2 = *(const ulonglong2*)&XS[dd * 68 + tx * 4];
            ull a0 = pack2(a.x), a1 = pack2(a.y), a2 = pack2(a.z), a3 = pack2(a.w);
            ffma2(acc[0][0], a0, f2.x); ffma2(acc[0][1], a0, f2.y);
            ffma2(acc[1][0], a1, f2.x); ffma2(acc[1][1], a1, f2.y);
            ffma2(acc[2][0], a2, f2.x); ffma2(acc[2][1], a2, f2.y);
            ffma2(acc[3][0], a3, f2.x); ffma2(acc[3][1], a3, f2.y);
        }
        __syncthreads();
    }

#pragma unroll
    for (int i = 0; i < 4; i++)
#pragma unroll
        for (int p = 0; p < 2; p++) {
            float2 u = unpack2(acc[i][p]);
            SC[(ty * 4 + i) * 68 + tx * 4 + 2 * p]     = u.x;
            SC[(ty * 4 + i) * 68 + tx * 4 + 2 * p + 1] = u.y;
        }
    __syncthreads();

    if (t < 64) {
        const int n = t;
        float mx = -1e30f;
#pragma unroll 8
        for (int k = 0; k < 64; k++) mx = fmaxf(mx, SC[k * 68 + n]);
        float s = 0.0f;
#pragma unroll 8
        for (int k = 0; k < 64; k++) {
            float e = __expf(SC[k * 68 + n] - mx);
            SC[k * 68 + n] = e;
            s += e;
        }
        inv_sum[n] = 1.0f / s;
    }
    __syncthreads();
    if (t < 64) {
        const int k = t;
        float s = 0.0f;
#pragma unroll 8
        for (int nn = 0; nn < 64; nn++) {
            float a = SC[k * 68 + nn] * inv_sum[nn];
            SC[k * 68 + nn] = a;
            s += a;
        }
        atomicAdd(&g_asum[b * 64 + k], s);
    }
    __syncthreads();
    {
        float tmp[16];
#pragma unroll
        for (int i = 0; i < 16; i++) {
            const int idx = t + i * 256;
            tmp[i] = SC[(idx >> 6) * 68 + (idx & 63)];
        }
        __syncthreads();
#pragma unroll
        for (int i = 0; i < 16; i++) {
            const int idx = t + i * 256;
            SC[(idx & 63) * 68 + (idx >> 6)] = tmp[i];
        }
    }

    auto stage2 = [&](int tile, int buf) {
        const int d0 = tile * 64;
        const uint32_t bx = buf ? sx1 : sx0;
#pragma unroll
        for (int i = 0; i < 4; i++) {
            const int dd = qdd + i * 16;
            cpa16(bx + (uint32_t)((dd * 68 + qn4 * 4) * 4),
                  xb + (size_t)(d0 + dd) * 1600 + n0 + qn4 * 4);
        }
        cpa_commit();
    };

    float* vp = g_vpart + ((size_t)blockIdx.x * 8 + b) * 32768;
    __syncthreads();
    stage2(0, 0);
    for (int tile = 0; tile < 8; tile++) {
        const int buf = tile & 1;
        if (tile < 7) {
            stage2(tile + 1, buf ^ 1);
            asm volatile("cp.async.wait_group 1;");
        } else {
            asm volatile("cp.async.wait_group 0;");
        }
        __syncthreads();

        const float* XS2 = buf ? XB1 : XB0;
        ull acc2[4][2];
#pragma unroll
        for (int i = 0; i < 4; i++) { acc2[i][0] = 0ULL; acc2[i][1] = 0ULL; }
#pragma unroll 4
        for (int nn = 0; nn < 64; nn++) {
            ulonglong2 a2 = *(const ulonglong2*)&SC[nn * 68 + tx * 4];
            ull f0 = pack2(XS2[(ty * 4 + 0) * 68 + nn]);
            ull f1 = pack2(XS2[(ty * 4 + 1) * 68 + nn]);
            ull f2p = pack2(XS2[(ty * 4 + 2) * 68 + nn]);
            ull f3 = pack2(XS2[(ty * 4 + 3) * 68 + nn]);
            ffma2(acc2[0][0], f0, a2.x);  ffma2(acc2[0][1], f0, a2.y);
            ffma2(acc2[1][0], f1, a2.x);  ffma2(acc2[1][1], f1, a2.y);
            ffma2(acc2[2][0], f2p, a2.x); ffma2(acc2[2][1], f2p, a2.y);
            ffma2(acc2[3][0], f3, a2.x);  ffma2(acc2[3][1], f3, a2.y);
        }
        const int d0 = tile * 64;
#pragma unroll
        for (int i = 0; i < 4; i++) {
            const int d = d0 + ty * 4 + i;
            float2 lo = unpack2(acc2[i][0]);
            float2 hi = unpack2(acc2[i][1]);
            float4 o; o.x = lo.x; o.y = lo.y; o.z = hi.x; o.w = hi.y;
            *(float4*)&vp[d * 64 + tx * 4] = o;
        }
        __syncthreads();
    }
}

// ---------------- post: sum partials + centers fold + norms + scale (one kernel) ----------------
// grid (32, 8). block 256; one float4 per thread. Device-side release via per-batch counter.
__global__ __launch_bounds__(256) void k_post(const float* __restrict__ centers) {
    const int b = blockIdx.y;
    const int t = threadIdx.x;
    const int i4 = blockIdx.x * 256 + t;   // float4 index within batch (0..8191)
    const int q = t & 15;                  // k4 group

    const float4* c4p = (const float4*)centers;
    const float4* A4p = (const float4*)(g_asum + b * 64);

    // sum 25 partials + centers fold (keep v in registers)
    float4 v = make_float4(0.f, 0.f, 0.f, 0.f);
#pragma unroll
    for (int s = 0; s < 25; s++) {
        float4 p = *(const float4*)(g_vpart + ((size_t)s * 8 + b) * 32768 + (size_t)i4 * 4);
        v.x += p.x; v.y += p.y; v.z += p.z; v.w += p.w;
    }
    const float4 A4 = A4p[q];
    const float4 c = c4p[i4];
    v.x -= A4.x * c.x; v.y -= A4.y * c.y; v.z -= A4.z * c.z; v.w -= A4.w * c.w;

    // per-k sum of squares -> g_ksum atomics
    __shared__ __align__(16) float4 red[256];
    red[t] = make_float4(v.x * v.x, v.y * v.y, v.z * v.z, v.w * v.w);
    __syncthreads();
    if (t < 16) {
        float4 s = make_float4(0.f, 0.f, 0.f, 0.f);
#pragma unroll
        for (int j = 0; j < 16; j++) {
            float4 r = red[t + j * 16];
            s.x += r.x; s.y += r.y; s.z += r.z; s.w += r.w;
        }
        atomicAdd(&g_ksum[b * 64 + t * 4 + 0], s.x);
        atomicAdd(&g_ksum[b * 64 + t * 4 + 1], s.y);
        atomicAdd(&g_ksum[b * 64 + t * 4 + 2], s.z);
        atomicAdd(&g_ksum[b * 64 + t * 4 + 3], s.w);
    }
    __threadfence();
    __syncthreads();

    // release: wait for all 32 blocks of this batch
    if (t == 0) {
        atomicAdd(&g_cntb[b], 1u);
        while (*(volatile unsigned*)&g_cntb[b] < 32u) { }
    }
    __syncthreads();
    __threadfence();

    // compute combined scale (intra-norm x global norm)
    __shared__ float sc_s[64];
    __shared__ float wred[2];
    float inv = 0.0f, contrib = 0.0f;
    if (t < 64) {
        float kv = *(volatile float*)&g_ksum[b * 64 + t];
        inv = 1.0f / fmaxf(sqrtf(kv), EPSN);
        contrib = kv * inv * inv;
    }
    float csum = contrib;
#pragma unroll
    for (int off = 16; off; off >>= 1) csum += __shfl_xor_sync(0xffffffffu, csum, off);
    if (t < 64 && (t & 31) == 0) wred[t >> 5] = csum;
    __syncthreads();
    if (t < 64) {
        float g = wred[0] + wred[1];
        sc_s[t] = inv * (1.0f / fmaxf(sqrtf(g), EPSN));
    }
    __syncthreads();

    // scale register copy, single write to g_vlad
    float4 sc4 = *(const float4*)&sc_s[q * 4];
    v.x *= sc4.x; v.y *= sc4.y; v.z *= sc4.z; v.w *= sc4.w;
    ((float4*)(g_vlad + (size_t)b * 32768))[i4] = v;
}

// ---------------- whitening GEMM: 32 rows/CTA, K-split 2, 5-stage ring, 1 sync/tile ----------------
// grid 256 = 128 rowtiles x 2 K-halves. block 256 (8 warps x 4 rows). 100KB dyn smem, occ 2.
__global__ __launch_bounds__(256, 2) void k_whiten(const float* __restrict__ W) {
    extern __shared__ __align__(16) float smw[];
    // W stages: [5][4096] floats at 0; D stages: [5][1024] floats at 20480

    const int rowtile = blockIdx.x >> 1;
    const int ks = blockIdx.x & 1;
    const int o0 = rowtile * 32;
    const int jbase = ks * 16384;

    const int t = threadIdx.x;
    const int lane = t & 31;
    const int warp = t >> 5;
    const int r0 = warp * 4;
    const int c = lane * 4;
    const int wr = t >> 5;
    const int wc4 = t & 31;

    ull acc[4][8];
#pragma unroll
    for (int r = 0; r < 4; r++)
#pragma unroll
        for (int bb = 0; bb < 8; bb++) acc[r][bb] = 0ULL;

    const uint32_t sbase = (uint32_t)__cvta_generic_to_shared(smw);
    const float* Wbase = W + (size_t)o0 * 32768 + jbase;
    const float* Dbase = g_vlad + jbase;

    auto stage = [&](int tile, int buf) {
        const int jc = tile * 128 + wc4 * 4;
#pragma unroll
        for (int i = 0; i < 4; i++) {
            const int r = wr + i * 8;
            cpa16(sbase + (uint32_t)((buf * 4096 + r * 128 + wc4 * 4) * 4),
                  Wbase + (size_t)r * 32768 + jc);
        }
        cpa16(sbase + (uint32_t)((20480 + buf * 1024 + wr * 128 + wc4 * 4) * 4),
              Dbase + (size_t)wr * 32768 + jc);
        cpa_commit();
    };

    stage(0, 0); stage(1, 1); stage(2, 2); stage(3, 3);

    int buf = 0, nbuf = 4;
    for (int tile = 0; tile < 128; tile++) {
        const int rem = 127 - tile;
        if (rem >= 3)      asm volatile("cp.async.wait_group 3;");
        else if (rem == 2) asm volatile("cp.async.wait_group 2;");
        else if (rem == 1) asm volatile("cp.async.wait_group 1;");
        else               asm volatile("cp.async.wait_group 0;");
        __syncthreads();
        // safe: stage target buffer == (tile-1) mod 5; all warps finished reading it pre-sync
        if (tile + 4 < 128) {
            stage(tile + 4, nbuf);
            if (++nbuf == 5) nbuf = 0;
        }

        const float* Wt = smw + buf * 4096;
        const float* Dt = smw + 20480 + buf * 1024;
        if (++buf == 5) buf = 0;

        ulonglong2 w2[4];
#pragma unroll
        for (int r = 0; r < 4; r++)
            w2[r] = *(const ulonglong2*)&Wt[(r0 + r) * 128 + c];
#pragma unroll
        for (int bb = 0; bb < 8; bb++) {
            ulonglong2 d2 = *(const ulonglong2*)&Dt[bb * 128 + c];
#pragma unroll
            for (int r = 0; r < 4; r++) {
                ffma2(acc[r][bb], w2[r].x, d2.x);
                ffma2(acc[r][bb], w2[r].y, d2.y);
            }
        }
    }

    float accf[4][8];
#pragma unroll
    for (int r = 0; r < 4; r++)
#pragma unroll
        for (int bb = 0; bb < 8; bb++) {
            float2 f = unpack2(acc[r][bb]);
            float v = f.x + f.y;
#pragma unroll
            for (int off = 16; off; off >>= 1)
                v += __shfl_xor_sync(0xffffffffu, v, off);
            accf[r][bb] = v;
        }

    const int rr = lane >> 3;
    const int bsel = lane & 7;
    float res = 0.0f;
#pragma unroll
    for (int r = 0; r < 4; r++)
#pragma unroll
        for (int bb = 0; bb < 8; bb++)
            if (r == rr && bb == bsel) res = accf[r][bb];

    g_wpart[((size_t)ks * 8 + bsel) * 4096 + o0 + r0 + rr] = res;
}

// ---------------- combine 2 K-partials + bias + final per-row L2 norm ----------------
__global__ __launch_bounds__(256) void k_final(const float* __restrict__ bias,
                                               float* __restrict__ out) {
    const int b = blockIdx.x;
    float v[16];
    float ss = 0.0f;
#pragma unroll
    for (int t = 0; t < 16; t++) {
        const int o = threadIdx.x + t * 256;
        float val = g_wpart[(size_t)b * 4096 + o]
                  + g_wpart[(size_t)(8 + b) * 4096 + o]
                  + bias[o];
        v[t] = val;
        ss += val * val;
    }
#pragma unroll
    for (int off = 16; off; off >>= 1) ss += __shfl_xor_sync(0xffffffffu, ss, off);
    __shared__ float r[8];
    __shared__ float sc;
    const int lane = threadIdx.x & 31, warp = threadIdx.x >> 5;
    if (lane == 0) r[warp] = ss;
    __syncthreads();
    if (threadIdx.x == 0) {
        float tt = 0.0f;
#pragma unroll
        for (int i = 0; i < 8; i++) tt += r[i];
        sc = 1.0f / fmaxf(sqrtf(tt), EPSN);
    }
    __syncthreads();
    float* ob = out + (size_t)b * 4096;
#pragma unroll
    for (int t = 0; t < 16; t++) ob[threadIdx.x + t * 256] = v[t] * sc;
}

// ---------------- launch ----------------
extern "C" void kernel_launch(void* const* d_in, const int* in_sizes, int n_in,
                              void* d_out, int out_size) {
    const float* x        = (const float*)d_in[0];
    const float* conv_w   = (const float*)d_in[1];
    const float* centers  = (const float*)d_in[2];
    const float* whiten_w = (const float*)d_in[3];
    const float* whiten_b = (const float*)d_in[4];
    float* out = (float*)d_out;

    static int attr_set = 0;
    if (!attr_set) {
        cudaFuncSetAttribute(k_whiten, cudaFuncAttributeMaxDynamicSharedMemorySize, 102400);
        cudaFuncSetAttribute(k_fused, cudaFuncAttributeMaxDynamicSharedMemorySize, 87296);
        attr_set = 1;
    }

    k_prep<<<64, 512>>>(conv_w);
    k_fused<<<dim3(25, 8), 256, 87296>>>(x);
    k_post<<<dim3(32, 8), 256>>>(centers);
    k_whiten<<<256, 256, 102400>>>(whiten_w);
    k_final<<<8, 256>>>(whiten_b, out);
}